// round 8
// baseline (speedup 1.0000x reference)
#include <cuda_runtime.h>
#include <math.h>

#define NN 100000
#define EE 3200000
#define HID 16
#define NCLS 10
#define KK 50000
#define SSIZE 131072
#define TILE 4096
#define SBLK 1024
#define NBLK 98   // ceil(100000/1024)

typedef unsigned long long ull;

__device__ float  d_h0[NN * HID];
__device__ float4 d_g0[NN * 4];        // dinv[n] * h0[n][:]  (float4 per quad)
__device__ float  d_h[NN * HID];
__device__ int    d_cnt[NN];
__device__ int    d_rowptr[NN + 1];
__device__ int    d_cursor[NN];
__device__ float  d_dinv[NN];
__device__ int    d_csr[EE];
__device__ float  d_spart[NN];
__device__ float  d_t2[NN];
__device__ float  d_s[NN];
__device__ ull    d_keys[SSIZE];
__device__ int    d_nidx[NN];
__device__ int    d_perm[KK];
__device__ float  d_h2[KK * NCLS];
__device__ float  d_dinv2[KK];
__device__ int    d_bsum[NBLK];
__device__ int    d_boff[NBLK];

// Kahan compensated add (safe under FMA contraction: no mul inside)
__device__ __forceinline__ void kadd(float& s, float& c, float v) {
    float y = v - c;
    float t = s + y;
    c = (t - s) - y;
    s = t;
}
__device__ __forceinline__ void kadd4(float4& s, float4& c, float4 v) {
    kadd(s.x, c.x, v.x); kadd(s.y, c.y, v.y);
    kadd(s.z, c.z, v.z); kadd(s.w, c.w, v.w);
}

// accurate fp32 rsqrt: hardware approx + one Newton step
__device__ __forceinline__ float rsqrt_acc(float x) {
    float r = rsqrtf(x);
    return r * (1.5f - 0.5f * x * r * r);
}

__global__ void kinitA() {
    int i = blockIdx.x * blockDim.x + threadIdx.x;
    if (i < SSIZE) d_keys[i] = 0ull;
}

__global__ void kinitB() {
    int i = blockIdx.x * blockDim.x + threadIdx.x;
    if (i < NN) d_cnt[i] = 0;
}

// h0 = x @ w1 : smem-tiled. 512 nodes/block, 128 threads, 4 nodes x 16 ch per
// thread, k staged in 8 chunks of 16 through xs[512][17].
__global__ void __launch_bounds__(128) kgemm1(const float* __restrict__ x,
                                              const float* __restrict__ w1) {
    __shared__ float xs[512 * 17];
    __shared__ __align__(16) float ws[2048];
    int t = threadIdx.x;
    for (int i = t; i < 512; i += 128)
        ((float4*)ws)[i] = ((const float4*)w1)[i];
    int base = blockIdx.x * 512;
    float acc[4][16];
#pragma unroll
    for (int i = 0; i < 4; i++)
#pragma unroll
        for (int c = 0; c < 16; c++) acc[i][c] = 0.f;

    for (int ck = 0; ck < 8; ck++) {
        __syncthreads();
#pragma unroll
        for (int it = 0; it < 16; it++) {
            int idx = it * 128 + t;
            int row = idx >> 2, q = idx & 3;
            int rg = base + row; if (rg > NN - 1) rg = NN - 1;
            float4 v = ((const float4*)x)[rg * 32 + ck * 4 + q];
            int o = row * 17 + q * 4;
            xs[o] = v.x; xs[o + 1] = v.y; xs[o + 2] = v.z; xs[o + 3] = v.w;
        }
        __syncthreads();
#pragma unroll 4
        for (int k = 0; k < 16; k++) {
            const float4* wr = (const float4*)(ws + (ck * 16 + k) * 16);
            float4 w0 = wr[0], w1v = wr[1], w2v = wr[2], w3v = wr[3];
#pragma unroll
            for (int i = 0; i < 4; i++) {
                float xv = xs[(t + 128 * i) * 17 + k];
                acc[i][0]  += xv * w0.x;  acc[i][1]  += xv * w0.y;
                acc[i][2]  += xv * w0.z;  acc[i][3]  += xv * w0.w;
                acc[i][4]  += xv * w1v.x; acc[i][5]  += xv * w1v.y;
                acc[i][6]  += xv * w1v.z; acc[i][7]  += xv * w1v.w;
                acc[i][8]  += xv * w2v.x; acc[i][9]  += xv * w2v.y;
                acc[i][10] += xv * w2v.z; acc[i][11] += xv * w2v.w;
                acc[i][12] += xv * w3v.x; acc[i][13] += xv * w3v.y;
                acc[i][14] += xv * w3v.z; acc[i][15] += xv * w3v.w;
            }
        }
    }
#pragma unroll
    for (int i = 0; i < 4; i++) {
        int n = base + t + 128 * i;
        if (n < NN) {
            float4* o = (float4*)(d_h0 + (size_t)n * HID);
#pragma unroll
            for (int q = 0; q < 4; q++)
                o[q] = make_float4(acc[i][q * 4], acc[i][q * 4 + 1],
                                   acc[i][q * 4 + 2], acc[i][q * 4 + 3]);
        }
    }
}

__global__ void kcount(const int* __restrict__ ei) {
    int e4 = blockIdx.x * blockDim.x + threadIdx.x;
    int4 d = ((const int4*)(ei + EE))[e4];
    atomicAdd(&d_cnt[d.x], 1);
    atomicAdd(&d_cnt[d.y], 1);
    atomicAdd(&d_cnt[d.z], 1);
    atomicAdd(&d_cnt[d.w], 1);
}

// ---- decoupled scan
__global__ void __launch_bounds__(SBLK) kscanA() {
    __shared__ int ws[32];
    int i = blockIdx.x * SBLK + threadIdx.x;
    int lane = threadIdx.x & 31, wd = threadIdx.x >> 5;
    int v = (i < NN) ? d_cnt[i] : 0;
    int s = v;
#pragma unroll
    for (int o = 16; o; o >>= 1) s += __shfl_xor_sync(0xFFFFFFFFu, s, o);
    if (lane == 0) ws[wd] = s;
    __syncthreads();
    if (wd == 0) {
        int s2 = ws[lane];
#pragma unroll
        for (int o = 16; o; o >>= 1) s2 += __shfl_xor_sync(0xFFFFFFFFu, s2, o);
        if (lane == 0) d_bsum[blockIdx.x] = s2;
    }
}

__global__ void kscanB() {
    __shared__ int sm[128];
    int t = threadIdx.x;
    int v = (t < NBLK) ? d_bsum[t] : 0;
    sm[t] = v;
    __syncthreads();
    for (int o = 1; o < 128; o <<= 1) {
        int y = (t >= o) ? sm[t - o] : 0;
        __syncthreads();
        sm[t] += y;
        __syncthreads();
    }
    if (t < NBLK) d_boff[t] = sm[t] - v;
    if (t == NBLK - 1) d_rowptr[NN] = sm[t];
}

__global__ void __launch_bounds__(SBLK) kscanC() {
    __shared__ int ws[32];
    int i = blockIdx.x * SBLK + threadIdx.x;
    int lane = threadIdx.x & 31, wd = threadIdx.x >> 5;
    int v = (i < NN) ? d_cnt[i] : 0;
    int xv = v;
#pragma unroll
    for (int o = 1; o < 32; o <<= 1) {
        int y = __shfl_up_sync(0xFFFFFFFFu, xv, o);
        if (lane >= o) xv += y;
    }
    if (lane == 31) ws[wd] = xv;
    __syncthreads();
    if (wd == 0) {
        int s2 = ws[lane];
#pragma unroll
        for (int o = 1; o < 32; o <<= 1) {
            int y = __shfl_up_sync(0xFFFFFFFFu, s2, o);
            if (lane >= o) s2 += y;
        }
        ws[lane] = s2;
    }
    __syncthreads();
    int excl = xv - v + (wd > 0 ? ws[wd - 1] : 0) + d_boff[blockIdx.x];
    if (i < NN) {
        d_rowptr[i] = excl;
        d_cursor[i] = excl;
        d_dinv[i] = rsqrt_acc((float)(v + 1));
        d_nidx[i] = -1;
    }
}

// g0 = dinv * h0 (same products conv1 used to compute inline)
__global__ void kscale() {
    int idx = blockIdx.x * blockDim.x + threadIdx.x;  // node*4 + quad
    if (idx >= NN * 4) return;
    float dv = d_dinv[idx >> 2];
    float4 h = ((const float4*)d_h0)[idx];
    d_g0[idx] = make_float4(dv * h.x, dv * h.y, dv * h.z, dv * h.w);
}

__global__ void kscatter(const int* __restrict__ ei) {
    int e4 = blockIdx.x * blockDim.x + threadIdx.x;
    int4 s = ((const int4*)ei)[e4];
    int4 d = ((const int4*)(ei + EE))[e4];
    d_csr[atomicAdd(&d_cursor[d.x], 1)] = s.x;
    d_csr[atomicAdd(&d_cursor[d.y], 1)] = s.y;
    d_csr[atomicAdd(&d_cursor[d.z], 1)] = s.z;
    d_csr[atomicAdd(&d_cursor[d.w], 1)] = s.w;
}

// conv1 (+relu): warp per node; 8 edges x 4 quads per iteration, float4
// gathers of premultiplied g0, dual Kahan chains; score linear terms fused.
__global__ void kconv1(const float* __restrict__ b1, const float* __restrict__ pw1,
                       const float* __restrict__ pw2, const float* __restrict__ pb) {
    int gw = (blockIdx.x * blockDim.x + threadIdx.x) >> 5;
    if (gw >= NN) return;
    int lane = threadIdx.x & 31;
    int stripe = lane & 7, quad = lane >> 3;
    int st = d_rowptr[gw], en = d_rowptr[gw + 1];
    float4 s0 = {0,0,0,0}, c0 = {0,0,0,0};
    float4 s1 = {0,0,0,0}, c1 = {0,0,0,0};
    for (int e0 = st; e0 < en; e0 += 16) {
        int ea = e0 + stripe, eb = e0 + 8 + stripe;
        int na = (ea < en) ? d_csr[ea] : -1;
        int nb = (eb < en) ? d_csr[eb] : -1;
        if (na >= 0) kadd4(s0, c0, d_g0[na * 4 + quad]);
        if (nb >= 0) kadd4(s1, c1, d_g0[nb * 4 + quad]);
    }
    kadd4(s0, c0, s1);
    kadd4(s0, c0, make_float4(-c1.x, -c1.y, -c1.z, -c1.w));
#pragma unroll
    for (int o = 1; o <= 4; o <<= 1) {
        float4 os, oc;
        os.x = __shfl_xor_sync(0xFFFFFFFFu, s0.x, o);
        os.y = __shfl_xor_sync(0xFFFFFFFFu, s0.y, o);
        os.z = __shfl_xor_sync(0xFFFFFFFFu, s0.z, o);
        os.w = __shfl_xor_sync(0xFFFFFFFFu, s0.w, o);
        oc.x = __shfl_xor_sync(0xFFFFFFFFu, c0.x, o);
        oc.y = __shfl_xor_sync(0xFFFFFFFFu, c0.y, o);
        oc.z = __shfl_xor_sync(0xFFFFFFFFu, c0.z, o);
        oc.w = __shfl_xor_sync(0xFFFFFFFFu, c0.w, o);
        kadd4(s0, c0, os);
        kadd4(s0, c0, make_float4(-oc.x, -oc.y, -oc.z, -oc.w));
    }
    float4 a = make_float4(s0.x - c0.x, s0.y - c0.y, s0.z - c0.z, s0.w - c0.w);
    float degf = (float)(en - st + 1);
    float dv = d_dinv[gw];
    float4 h0v = ((const float4*)d_h0)[gw * 4 + quad];
    float4 b1v = ((const float4*)b1)[quad];
    float4 hv;
    hv.x = fmaxf(dv * a.x + h0v.x / degf + b1v.x, 0.f);
    hv.y = fmaxf(dv * a.y + h0v.y / degf + b1v.y, 0.f);
    hv.z = fmaxf(dv * a.z + h0v.z / degf + b1v.z, 0.f);
    hv.w = fmaxf(dv * a.w + h0v.w / degf + b1v.w, 0.f);
    if (stripe == 0) ((float4*)d_h)[gw * 4 + quad] = hv;
    float4 p1 = ((const float4*)pw1)[quad];
    float4 p2 = ((const float4*)pw2)[quad];
    float u1 = hv.x * p1.x + hv.y * p1.y + hv.z * p1.z + hv.w * p1.w;
    float u2 = hv.x * p2.x + hv.y * p2.y + hv.z * p2.z + hv.w * p2.w;
#pragma unroll
    for (int o = 8; o <= 16; o <<= 1) {
        u1 += __shfl_xor_sync(0xFFFFFFFFu, u1, o);
        u2 += __shfl_xor_sync(0xFFFFFFFFu, u2, o);
    }
    if (lane == 0) { d_spart[gw] = u1 + pb[0]; d_t2[gw] = u2; }
}

// score = spart + sum_{in-neighbors} t2 (Kahan); build sort key
__global__ void kpool() {
    int gw = (blockIdx.x * blockDim.x + threadIdx.x) >> 5;
    if (gw >= NN) return;
    int lane = threadIdx.x & 31;
    int st = d_rowptr[gw], en = d_rowptr[gw + 1];
    float sum = 0.f, comp = 0.f;
    for (int e = st + lane; e < en; e += 32) kadd(sum, comp, d_t2[d_csr[e]]);
#pragma unroll
    for (int o = 16; o; o >>= 1) {
        float os = __shfl_xor_sync(0xFFFFFFFFu, sum, o);
        float oc = __shfl_xor_sync(0xFFFFFFFFu, comp, o);
        kadd(sum, comp, os); kadd(sum, comp, -oc);
    }
    if (lane == 0) {
        float sv = d_spart[gw] + (sum - comp);
        d_s[gw] = sv;
        unsigned u = __float_as_uint(sv);
        u = (u & 0x80000000u) ? ~u : (u | 0x80000000u);
        d_keys[gw] = ((ull)u << 32) | (ull)(~(unsigned)gw);
    }
}

// bitonic sort, descending, SSIZE unique keys
__global__ void __launch_bounds__(1024) ksort_init() {
    __shared__ ull sk[TILE];
    int base = blockIdx.x * TILE;
    for (int i = threadIdx.x; i < TILE; i += 1024) sk[i] = d_keys[base + i];
    __syncthreads();
    for (int k = 2; k <= TILE; k <<= 1)
        for (int j = k >> 1; j > 0; j >>= 1) {
            for (int i = threadIdx.x; i < TILE; i += 1024) {
                int p = i ^ j;
                if (p > i) {
                    bool desc = (((base + i) & k) == 0);
                    ull A = sk[i], B = sk[p];
                    if ((A < B) == desc) { sk[i] = B; sk[p] = A; }
                }
            }
            __syncthreads();
        }
    for (int i = threadIdx.x; i < TILE; i += 1024) d_keys[base + i] = sk[i];
}

// all global steps (j >= 4096) of phase k, fused.
__global__ void __launch_bounds__(1024) kcol(int k) {
    __shared__ ull sk[4096];          // [m][low] : 32 x 128
    int lowbase = blockIdx.x * 128;
    for (int idx = threadIdx.x; idx < 4096; idx += 1024) {
        int m = idx >> 7, low = idx & 127;
        sk[idx] = d_keys[m * 4096 + lowbase + low];
    }
    __syncthreads();
    int kp = k >> 12;                 // k' in units of 4096
    for (int jp = kp >> 1; jp >= 1; jp >>= 1) {
        for (int q = threadIdx.x; q < 2048; q += 1024) {
            int low = q & 127;
            int mg = q >> 7;          // 0..15
            int m = ((mg & ~(jp - 1)) << 1) | (mg & (jp - 1));
            int p = m | jp;
            bool desc = ((m & kp) == 0);
            ull A = sk[m * 128 + low], B = sk[p * 128 + low];
            if ((A < B) == desc) { sk[m * 128 + low] = B; sk[p * 128 + low] = A; }
        }
        __syncthreads();
    }
    for (int idx = threadIdx.x; idx < 4096; idx += 1024) {
        int m = idx >> 7, low = idx & 127;
        d_keys[m * 4096 + lowbase + low] = sk[idx];
    }
}

__global__ void __launch_bounds__(1024) ksort_merge(int k) {
    __shared__ ull sk[TILE];
    int base = blockIdx.x * TILE;
    for (int i = threadIdx.x; i < TILE; i += 1024) sk[i] = d_keys[base + i];
    __syncthreads();
    for (int j = TILE >> 1; j > 0; j >>= 1) {
        for (int i = threadIdx.x; i < TILE; i += 1024) {
            int p = i ^ j;
            if (p > i) {
                bool desc = (((base + i) & k) == 0);
                ull A = sk[i], B = sk[p];
                if ((A < B) == desc) { sk[i] = B; sk[p] = A; }
            }
        }
        __syncthreads();
    }
    for (int i = threadIdx.x; i < TILE; i += 1024) d_keys[base + i] = sk[i];
}

// top-K select: perm, inverse map, h2 = tanh(s) * (h @ w2)
__global__ void kselect(const float* __restrict__ w2) {
    int r = (blockIdx.x * blockDim.x + threadIdx.x) >> 5;
    if (r >= KK) return;
    int lane = threadIdx.x & 31;
    ull key = d_keys[r];
    int idx = (int)(~(unsigned)(key & 0xFFFFFFFFull));
    if (lane == 0) { d_nidx[idx] = r; d_perm[r] = idx; }
    if (lane < NCLS) {
        float th = tanhf(d_s[idx]);
        float acc = 0.f;
#pragma unroll
        for (int j = 0; j < HID; j++)
            acc += d_h[idx * HID + j] * w2[j * NCLS + lane];
        d_h2[r * NCLS + lane] = th * acc;
    }
}

// surviving-degree of kept nodes; pre-scale h2 rows by dinv2
__global__ void kdeg2() {
    int r = (blockIdx.x * blockDim.x + threadIdx.x) >> 5;
    if (r >= KK) return;
    int lane = threadIdx.x & 31;
    int i = d_perm[r];
    int st = d_rowptr[i], en = d_rowptr[i + 1];
    int cnt = 0;
    for (int e = st + lane; e < en; e += 32) cnt += (d_nidx[d_csr[e]] >= 0);
#pragma unroll
    for (int o = 16; o; o >>= 1) cnt += __shfl_xor_sync(0xFFFFFFFFu, cnt, o);
    float d2 = rsqrt_acc((float)(cnt + 1));
    if (lane == 0) d_dinv2[r] = d2;
    if (lane < NCLS) d_h2[r * NCLS + lane] *= d2;
}

// conv2: lane-parallel edge gather + relu + log_softmax
__global__ void kconv2(const float* __restrict__ b2, float* __restrict__ out) {
    __shared__ float red[8][NCLS];
    int r = (blockIdx.x * blockDim.x + threadIdx.x) >> 5;
    if (r >= KK) return;
    int lane = threadIdx.x & 31, wip = (threadIdx.x >> 5) & 7;
    int i = d_perm[r];
    int st = d_rowptr[i], en = d_rowptr[i + 1];
    float acc[NCLS];
#pragma unroll
    for (int c = 0; c < NCLS; c++) acc[c] = 0.f;
    for (int e = st + lane; e < en; e += 32) {
        int n0 = d_nidx[d_csr[e]];
        if (n0 >= 0) {
            const float* row = d_h2 + n0 * NCLS;
#pragma unroll
            for (int c = 0; c < NCLS; c++) acc[c] += row[c];
        }
    }
#pragma unroll
    for (int c = 0; c < NCLS; c++)
#pragma unroll
        for (int o = 16; o; o >>= 1)
            acc[c] += __shfl_xor_sync(0xFFFFFFFFu, acc[c], o);
    if (lane == 0) {
#pragma unroll
        for (int c = 0; c < NCLS; c++) red[wip][c] = acc[c];
    }
    __syncwarp();
    bool act = lane < NCLS;
    float v = act
        ? fmaxf(d_dinv2[r] * (red[wip][lane] + d_h2[r * NCLS + lane]) + b2[lane], 0.f)
        : -1e30f;
    float m = v;
#pragma unroll
    for (int o = 8; o; o >>= 1)
        m = fmaxf(m, __shfl_xor_sync(0xFFFFFFFFu, m, o, 16));
    float ex = act ? expf(v - m) : 0.f;
#pragma unroll
    for (int o = 8; o; o >>= 1)
        ex += __shfl_xor_sync(0xFFFFFFFFu, ex, o, 16);
    if (act) out[r * NCLS + lane] = v - m - logf(ex);
}

extern "C" void kernel_launch(void* const* d_in, const int* in_sizes, int n_in,
                              void* d_out, int out_size) {
    const float* x  = (const float*)d_in[0];
    const int*   ei = (const int*)d_in[1];
    const float* w1 = (const float*)d_in[2];
    const float* b1 = (const float*)d_in[3];
    const float* pw1 = (const float*)d_in[4];
    const float* pw2 = (const float*)d_in[5];
    const float* pb = (const float*)d_in[6];
    const float* w2 = (const float*)d_in[7];
    const float* b2 = (const float*)d_in[8];
    float* out = (float*)d_out;

    kinitA<<<SSIZE / 256, 256>>>();
    kinitB<<<(NN + 255) / 256, 256>>>();
    kcount<<<EE / 1024, 256>>>(ei);
    kgemm1<<<(NN + 511) / 512, 128>>>(x, w1);   // slot 4: gets profiled
    kscanA<<<NBLK, SBLK>>>();
    kscanB<<<1, 128>>>();
    kscanC<<<NBLK, SBLK>>>();
    kscale<<<(NN * 4 + 255) / 256, 256>>>();
    kscatter<<<EE / 1024, 256>>>(ei);
    kconv1<<<NN * 32 / 256, 256>>>(b1, pw1, pw2, pb);
    kpool<<<NN * 32 / 256, 256>>>();

    ksort_init<<<SSIZE / TILE, 1024>>>();
    for (int k = TILE * 2; k <= SSIZE; k <<= 1) {
        kcol<<<SSIZE / 4096, 1024>>>(k);
        ksort_merge<<<SSIZE / TILE, 1024>>>(k);
    }

    kselect<<<KK * 32 / 256, 256>>>(w2);
    kdeg2<<<KK * 32 / 256, 256>>>();
    kconv2<<<KK * 32 / 256, 256>>>(b2, out);
}

// round 9
// speedup vs baseline: 1.0691x; 1.0691x over previous
#include <cuda_runtime.h>
#include <math.h>

#define NN 100000
#define EE 3200000
#define HID 16
#define NCLS 10
#define KK 50000
#define SSIZE 131072
#define TILE 4096
#define SBLK 1024
#define NBLK 98   // ceil(100000/1024)

typedef unsigned long long ull;

__device__ float  d_h0[NN * HID];
__device__ float  d_h[NN * HID];
__device__ int    d_cnt[NN];
__device__ int    d_rowptr[NN + 1];
__device__ int    d_cursor[NN];
__device__ float  d_dinv[NN];
__device__ int    d_csr[EE];
__device__ float  d_spart[NN];
__device__ float  d_t2[NN];
__device__ float  d_s[NN];
__device__ ull    d_keys[SSIZE];
__device__ int    d_nidx[NN];
__device__ int    d_perm[KK];
__device__ float  d_h2[KK * NCLS];
__device__ float  d_dinv2[KK];
__device__ int    d_bsum[NBLK];
__device__ int    d_boff[NBLK];

// Kahan compensated add (safe under FMA contraction: no mul inside)
__device__ __forceinline__ void kadd(float& s, float& c, float v) {
    float y = v - c;
    float t = s + y;
    c = (t - s) - y;
    s = t;
}

// accurate fp32 rsqrt: hardware approx + one Newton step
__device__ __forceinline__ float rsqrt_acc(float x) {
    float r = rsqrtf(x);
    return r * (1.5f - 0.5f * x * r * r);
}

__global__ void kinit() {
    int i = blockIdx.x * blockDim.x + threadIdx.x;
    if (i < SSIZE) d_keys[i] = 0ull;
    if (i < NN) d_cnt[i] = 0;
}

// h0 = x @ w1 : f32x2 packed-FMA tiled GEMM. 256 nodes/block, 256 threads,
// 1 node/thread, 8 packed accumulators (16 channels). k staged in 8 chunks of
// 16 via xs[256][17] (coalesced LDG.128, conflict-free LDS.32); w pairs read
// packed via uniform LDS.64.
__global__ void __launch_bounds__(256) kgemm1(const float* __restrict__ x,
                                              const float* __restrict__ w1) {
    __shared__ float xs[256 * 17];
    __shared__ __align__(16) float ws[2048];
    int t = threadIdx.x;
    for (int i = t; i < 512; i += 256)
        ((float4*)ws)[i] = ((const float4*)w1)[i];
    const ull* wsu = (const ull*)ws;
    int base = blockIdx.x * 256;
    ull acc[8];
#pragma unroll
    for (int p = 0; p < 8; p++) acc[p] = 0ull;

    for (int ck = 0; ck < 8; ck++) {
        __syncthreads();
#pragma unroll
        for (int it = 0; it < 4; it++) {
            int idx = it * 256 + t;           // 0..1023
            int row = idx >> 2, q = idx & 3;
            int rg = base + row; if (rg >= NN) rg = NN - 1;
            float4 v = ((const float4*)x)[rg * 32 + ck * 4 + q];
            int o = row * 17 + q * 4;
            xs[o] = v.x; xs[o + 1] = v.y; xs[o + 2] = v.z; xs[o + 3] = v.w;
        }
        __syncthreads();
#pragma unroll
        for (int k = 0; k < 16; k++) {
            float xv = xs[t * 17 + k];
            ull xx;
            asm("mov.b64 %0, {%1, %1};" : "=l"(xx) : "r"(__float_as_uint(xv)));
            int kk = ck * 16 + k;
#pragma unroll
            for (int p = 0; p < 8; p++) {
                ull wv = wsu[kk * 8 + p];
                asm("fma.rn.f32x2 %0, %1, %2, %0;"
                    : "+l"(acc[p]) : "l"(xx), "l"(wv));
            }
        }
    }
    int n = base + t;
    if (n < NN) {
        ull* o = (ull*)(d_h0 + (size_t)n * HID);
#pragma unroll
        for (int p = 0; p < 8; p++) o[p] = acc[p];
    }
}

__global__ void kcount(const int* __restrict__ ei) {
    int e4 = blockIdx.x * blockDim.x + threadIdx.x;
    int4 d = ((const int4*)(ei + EE))[e4];
    atomicAdd(&d_cnt[d.x], 1);
    atomicAdd(&d_cnt[d.y], 1);
    atomicAdd(&d_cnt[d.z], 1);
    atomicAdd(&d_cnt[d.w], 1);
}

// ---- decoupled scan
__global__ void __launch_bounds__(SBLK) kscanA() {
    __shared__ int ws[32];
    int i = blockIdx.x * SBLK + threadIdx.x;
    int lane = threadIdx.x & 31, wd = threadIdx.x >> 5;
    int v = (i < NN) ? d_cnt[i] : 0;
    int s = v;
#pragma unroll
    for (int o = 16; o; o >>= 1) s += __shfl_xor_sync(0xFFFFFFFFu, s, o);
    if (lane == 0) ws[wd] = s;
    __syncthreads();
    if (wd == 0) {
        int s2 = ws[lane];
#pragma unroll
        for (int o = 16; o; o >>= 1) s2 += __shfl_xor_sync(0xFFFFFFFFu, s2, o);
        if (lane == 0) d_bsum[blockIdx.x] = s2;
    }
}

__global__ void kscanB() {
    __shared__ int sm[128];
    int t = threadIdx.x;
    int v = (t < NBLK) ? d_bsum[t] : 0;
    sm[t] = v;
    __syncthreads();
    for (int o = 1; o < 128; o <<= 1) {
        int y = (t >= o) ? sm[t - o] : 0;
        __syncthreads();
        sm[t] += y;
        __syncthreads();
    }
    if (t < NBLK) d_boff[t] = sm[t] - v;
    if (t == NBLK - 1) d_rowptr[NN] = sm[t];
}

__global__ void __launch_bounds__(SBLK) kscanC() {
    __shared__ int ws[32];
    int i = blockIdx.x * SBLK + threadIdx.x;
    int lane = threadIdx.x & 31, wd = threadIdx.x >> 5;
    int v = (i < NN) ? d_cnt[i] : 0;
    int xv = v;
#pragma unroll
    for (int o = 1; o < 32; o <<= 1) {
        int y = __shfl_up_sync(0xFFFFFFFFu, xv, o);
        if (lane >= o) xv += y;
    }
    if (lane == 31) ws[wd] = xv;
    __syncthreads();
    if (wd == 0) {
        int s2 = ws[lane];
#pragma unroll
        for (int o = 1; o < 32; o <<= 1) {
            int y = __shfl_up_sync(0xFFFFFFFFu, s2, o);
            if (lane >= o) s2 += y;
        }
        ws[lane] = s2;
    }
    __syncthreads();
    int excl = xv - v + (wd > 0 ? ws[wd - 1] : 0) + d_boff[blockIdx.x];
    if (i < NN) {
        d_rowptr[i] = excl;
        d_cursor[i] = excl;
        d_dinv[i] = rsqrt_acc((float)(v + 1));
        d_nidx[i] = -1;
    }
}

__global__ void kscatter(const int* __restrict__ ei) {
    int e4 = blockIdx.x * blockDim.x + threadIdx.x;
    int4 s = ((const int4*)ei)[e4];
    int4 d = ((const int4*)(ei + EE))[e4];
    d_csr[atomicAdd(&d_cursor[d.x], 1)] = s.x;
    d_csr[atomicAdd(&d_cursor[d.y], 1)] = s.y;
    d_csr[atomicAdd(&d_cursor[d.z], 1)] = s.z;
    d_csr[atomicAdd(&d_cursor[d.w], 1)] = s.w;
}

// conv1 (+relu) fp32 Kahan accumulation, 4-way unrolled; score linear terms
__global__ void kconv1(const float* __restrict__ b1, const float* __restrict__ pw1,
                       const float* __restrict__ pw2, const float* __restrict__ pb) {
    int gw = (blockIdx.x * blockDim.x + threadIdx.x) >> 5;
    if (gw >= NN) return;
    int lane = threadIdx.x & 31, half = lane >> 4, ch = lane & 15;
    int st = d_rowptr[gw], en = d_rowptr[gw + 1];
    float s0a = 0.f, c0a = 0.f, s1a = 0.f, c1a = 0.f;
    float s2a = 0.f, c2a = 0.f, s3a = 0.f, c3a = 0.f;
    int e = st + half;
    for (; e + 6 < en; e += 8) {
        int n0 = d_csr[e], n1 = d_csr[e + 2], n2 = d_csr[e + 4], n3 = d_csr[e + 6];
        kadd(s0a, c0a, d_dinv[n0] * d_h0[n0 * HID + ch]);
        kadd(s1a, c1a, d_dinv[n1] * d_h0[n1 * HID + ch]);
        kadd(s2a, c2a, d_dinv[n2] * d_h0[n2 * HID + ch]);
        kadd(s3a, c3a, d_dinv[n3] * d_h0[n3 * HID + ch]);
    }
    for (; e < en; e += 2) {
        int n0 = d_csr[e];
        kadd(s0a, c0a, d_dinv[n0] * d_h0[n0 * HID + ch]);
    }
    kadd(s0a, c0a, s1a); kadd(s0a, c0a, -c1a);
    kadd(s0a, c0a, s2a); kadd(s0a, c0a, -c2a);
    kadd(s0a, c0a, s3a); kadd(s0a, c0a, -c3a);
    float os = __shfl_xor_sync(0xFFFFFFFFu, s0a, 16);
    float oc = __shfl_xor_sync(0xFFFFFFFFu, c0a, 16);
    kadd(s0a, c0a, os); kadd(s0a, c0a, -oc);
    float a = s0a - c0a;
    float degf = (float)(en - st + 1);
    float hv = d_dinv[gw] * a + d_h0[gw * HID + ch] / degf + b1[ch];
    hv = fmaxf(hv, 0.f);
    if (half == 0) d_h[gw * HID + ch] = hv;
    float u1 = hv * pw1[ch];
    float u2 = hv * pw2[ch];
#pragma unroll
    for (int o = 8; o; o >>= 1) {
        u1 += __shfl_xor_sync(0xFFFFFFFFu, u1, o);
        u2 += __shfl_xor_sync(0xFFFFFFFFu, u2, o);
    }
    if (lane == 0) { d_spart[gw] = u1 + pb[0]; d_t2[gw] = u2; }
}

// score = spart + sum_{in-neighbors} t2 (Kahan); build sort key
__global__ void kpool() {
    int gw = (blockIdx.x * blockDim.x + threadIdx.x) >> 5;
    if (gw >= NN) return;
    int lane = threadIdx.x & 31;
    int st = d_rowptr[gw], en = d_rowptr[gw + 1];
    float sum = 0.f, comp = 0.f;
    for (int e = st + lane; e < en; e += 32) kadd(sum, comp, d_t2[d_csr[e]]);
#pragma unroll
    for (int o = 16; o; o >>= 1) {
        float os = __shfl_xor_sync(0xFFFFFFFFu, sum, o);
        float oc = __shfl_xor_sync(0xFFFFFFFFu, comp, o);
        kadd(sum, comp, os); kadd(sum, comp, -oc);
    }
    if (lane == 0) {
        float sv = d_spart[gw] + (sum - comp);
        d_s[gw] = sv;
        unsigned u = __float_as_uint(sv);
        u = (u & 0x80000000u) ? ~u : (u | 0x80000000u);
        d_keys[gw] = ((ull)u << 32) | (ull)(~(unsigned)gw);
    }
}

// bitonic sort, descending, SSIZE unique keys
__global__ void __launch_bounds__(1024) ksort_init() {
    __shared__ ull sk[TILE];
    int base = blockIdx.x * TILE;
    for (int i = threadIdx.x; i < TILE; i += 1024) sk[i] = d_keys[base + i];
    __syncthreads();
    for (int k = 2; k <= TILE; k <<= 1)
        for (int j = k >> 1; j > 0; j >>= 1) {
            for (int i = threadIdx.x; i < TILE; i += 1024) {
                int p = i ^ j;
                if (p > i) {
                    bool desc = (((base + i) & k) == 0);
                    ull A = sk[i], B = sk[p];
                    if ((A < B) == desc) { sk[i] = B; sk[p] = A; }
                }
            }
            __syncthreads();
        }
    for (int i = threadIdx.x; i < TILE; i += 1024) d_keys[base + i] = sk[i];
}

// all global steps (j >= 4096) of phase k, fused.
__global__ void __launch_bounds__(1024) kcol(int k) {
    __shared__ ull sk[4096];          // [m][low] : 32 x 128
    int lowbase = blockIdx.x * 128;
    for (int idx = threadIdx.x; idx < 4096; idx += 1024) {
        int m = idx >> 7, low = idx & 127;
        sk[idx] = d_keys[m * 4096 + lowbase + low];
    }
    __syncthreads();
    int kp = k >> 12;                 // k' in units of 4096
    for (int jp = kp >> 1; jp >= 1; jp >>= 1) {
        for (int q = threadIdx.x; q < 2048; q += 1024) {
            int low = q & 127;
            int mg = q >> 7;          // 0..15
            int m = ((mg & ~(jp - 1)) << 1) | (mg & (jp - 1));
            int p = m | jp;
            bool desc = ((m & kp) == 0);
            ull A = sk[m * 128 + low], B = sk[p * 128 + low];
            if ((A < B) == desc) { sk[m * 128 + low] = B; sk[p * 128 + low] = A; }
        }
        __syncthreads();
    }
    for (int idx = threadIdx.x; idx < 4096; idx += 1024) {
        int m = idx >> 7, low = idx & 127;
        d_keys[m * 4096 + lowbase + low] = sk[idx];
    }
}

__global__ void __launch_bounds__(1024) ksort_merge(int k) {
    __shared__ ull sk[TILE];
    int base = blockIdx.x * TILE;
    for (int i = threadIdx.x; i < TILE; i += 1024) sk[i] = d_keys[base + i];
    __syncthreads();
    for (int j = TILE >> 1; j > 0; j >>= 1) {
        for (int i = threadIdx.x; i < TILE; i += 1024) {
            int p = i ^ j;
            if (p > i) {
                bool desc = (((base + i) & k) == 0);
                ull A = sk[i], B = sk[p];
                if ((A < B) == desc) { sk[i] = B; sk[p] = A; }
            }
        }
        __syncthreads();
    }
    for (int i = threadIdx.x; i < TILE; i += 1024) d_keys[base + i] = sk[i];
}

// top-K select: perm, inverse map, h2 = tanh(s) * (h @ w2)
__global__ void kselect(const float* __restrict__ w2) {
    int r = (blockIdx.x * blockDim.x + threadIdx.x) >> 5;
    if (r >= KK) return;
    int lane = threadIdx.x & 31;
    ull key = d_keys[r];
    int idx = (int)(~(unsigned)(key & 0xFFFFFFFFull));
    if (lane == 0) { d_nidx[idx] = r; d_perm[r] = idx; }
    if (lane < NCLS) {
        float th = tanhf(d_s[idx]);
        float acc = 0.f;
#pragma unroll
        for (int j = 0; j < HID; j++)
            acc += d_h[idx * HID + j] * w2[j * NCLS + lane];
        d_h2[r * NCLS + lane] = th * acc;
    }
}

// surviving-degree of kept nodes; pre-scale h2 rows by dinv2
__global__ void kdeg2() {
    int r = (blockIdx.x * blockDim.x + threadIdx.x) >> 5;
    if (r >= KK) return;
    int lane = threadIdx.x & 31;
    int i = d_perm[r];
    int st = d_rowptr[i], en = d_rowptr[i + 1];
    int cnt = 0;
    for (int e = st + lane; e < en; e += 32) cnt += (d_nidx[d_csr[e]] >= 0);
#pragma unroll
    for (int o = 16; o; o >>= 1) cnt += __shfl_xor_sync(0xFFFFFFFFu, cnt, o);
    float d2 = rsqrt_acc((float)(cnt + 1));
    if (lane == 0) d_dinv2[r] = d2;
    if (lane < NCLS) d_h2[r * NCLS + lane] *= d2;
}

// conv2: lane-parallel edge gather + relu + log_softmax
__global__ void kconv2(const float* __restrict__ b2, float* __restrict__ out) {
    __shared__ float red[8][NCLS];
    int r = (blockIdx.x * blockDim.x + threadIdx.x) >> 5;
    if (r >= KK) return;
    int lane = threadIdx.x & 31, wip = (threadIdx.x >> 5) & 7;
    int i = d_perm[r];
    int st = d_rowptr[i], en = d_rowptr[i + 1];
    float acc[NCLS];
#pragma unroll
    for (int c = 0; c < NCLS; c++) acc[c] = 0.f;
    for (int e = st + lane; e < en; e += 32) {
        int n0 = d_nidx[d_csr[e]];
        if (n0 >= 0) {
            const float* row = d_h2 + n0 * NCLS;
#pragma unroll
            for (int c = 0; c < NCLS; c++) acc[c] += row[c];
        }
    }
#pragma unroll
    for (int c = 0; c < NCLS; c++)
#pragma unroll
        for (int o = 16; o; o >>= 1)
            acc[c] += __shfl_xor_sync(0xFFFFFFFFu, acc[c], o);
    if (lane == 0) {
#pragma unroll
        for (int c = 0; c < NCLS; c++) red[wip][c] = acc[c];
    }
    __syncwarp();
    bool act = lane < NCLS;
    float v = act
        ? fmaxf(d_dinv2[r] * (red[wip][lane] + d_h2[r * NCLS + lane]) + b2[lane], 0.f)
        : -1e30f;
    float m = v;
#pragma unroll
    for (int o = 8; o; o >>= 1)
        m = fmaxf(m, __shfl_xor_sync(0xFFFFFFFFu, m, o, 16));
    float ex = act ? expf(v - m) : 0.f;
#pragma unroll
    for (int o = 8; o; o >>= 1)
        ex += __shfl_xor_sync(0xFFFFFFFFu, ex, o, 16);
    if (act) out[r * NCLS + lane] = v - m - logf(ex);
}

extern "C" void kernel_launch(void* const* d_in, const int* in_sizes, int n_in,
                              void* d_out, int out_size) {
    const float* x  = (const float*)d_in[0];
    const int*   ei = (const int*)d_in[1];
    const float* w1 = (const float*)d_in[2];
    const float* b1 = (const float*)d_in[3];
    const float* pw1 = (const float*)d_in[4];
    const float* pw2 = (const float*)d_in[5];
    const float* pb = (const float*)d_in[6];
    const float* w2 = (const float*)d_in[7];
    const float* b2 = (const float*)d_in[8];
    float* out = (float*)d_out;

    kinit<<<SSIZE / 256, 256>>>();
    kcount<<<EE / 1024, 256>>>(ei);
    kscanA<<<NBLK, SBLK>>>();
    kgemm1<<<(NN + 255) / 256, 256>>>(x, w1);   // slot 4: gets profiled
    kscanB<<<1, 128>>>();
    kscanC<<<NBLK, SBLK>>>();
    kscatter<<<EE / 1024, 256>>>(ei);
    kconv1<<<NN * 32 / 256, 256>>>(b1, pw1, pw2, pb);
    kpool<<<NN * 32 / 256, 256>>>();

    ksort_init<<<SSIZE / TILE, 1024>>>();
    for (int k = TILE * 2; k <= SSIZE; k <<= 1) {
        kcol<<<SSIZE / 4096, 1024>>>(k);
        ksort_merge<<<SSIZE / TILE, 1024>>>(k);
    }

    kselect<<<KK * 32 / 256, 256>>>(w2);
    kdeg2<<<KK * 32 / 256, 256>>>();
    kconv2<<<KK * 32 / 256, 256>>>(b2, out);
}

// round 10
// speedup vs baseline: 1.0777x; 1.0080x over previous
#include <cuda_runtime.h>
#include <math.h>

#define NN 100000
#define EE 3200000
#define HID 16
#define NCLS 10
#define KK 50000
#define SSIZE 131072
#define TILE 4096
#define SBLK 1024
#define NBLK 98   // ceil(100000/1024)

typedef unsigned long long ull;

__device__ float  d_h0[NN * HID];
__device__ float  d_h[NN * HID];
__device__ int    d_cnt[NN];
__device__ int    d_rowptr[NN + 1];
__device__ int    d_cursor[NN];
__device__ float  d_dinv[NN];
__device__ int    d_csr[EE];
__device__ float  d_spart[NN];
__device__ float  d_t2[NN];
__device__ float  d_s[NN];
__device__ ull    d_keys[SSIZE];
__device__ int    d_nidx[NN];
__device__ int    d_perm[KK];
__device__ float4 d_h2v[NN * 3];   // 12 floats per ORIGINAL node id; zero if dropped
__device__ float  d_dinv2[KK];
__device__ int    d_bsum[NBLK];
__device__ int    d_boff[NBLK];

// Kahan compensated add (safe under FMA contraction: no mul inside)
__device__ __forceinline__ void kadd(float& s, float& c, float v) {
    float y = v - c;
    float t = s + y;
    c = (t - s) - y;
    s = t;
}

// accurate fp32 rsqrt: hardware approx + one Newton step
__device__ __forceinline__ float rsqrt_acc(float x) {
    float r = rsqrtf(x);
    return r * (1.5f - 0.5f * x * r * r);
}

__global__ void kinit() {
    int i = blockIdx.x * blockDim.x + threadIdx.x;
    if (i < SSIZE) d_keys[i] = 0ull;
    if (i < NN) d_cnt[i] = 0;
    if (i < NN * 3) d_h2v[i] = make_float4(0.f, 0.f, 0.f, 0.f);
}

// h0 = x @ w1 : f32x2 packed FMA, 2 nodes x 16ch per thread, split-k over
// lane pairs (h = t&1 owns k-half h). 256 threads = 128 pairs = 256 nodes.
// ws has a 2-float gap at kk=64 so the two halves' broadcast LDS.64 hit
// disjoint banks; xs[1] is offset by 1 float for the same reason.
__global__ void __launch_bounds__(256) kgemm1(const float* __restrict__ x,
                                              const float* __restrict__ w1) {
    __shared__ __align__(16) float xsbuf[2 * (256 * 17) + 1];
    __shared__ __align__(16) float ws[2050];
    int t = threadIdx.x;
    for (int f = t; f < 2048; f += 256) {
        int kk = f >> 4;
        ws[f + ((kk >= 64) ? 2 : 0)] = w1[f];
    }
    const ull* wsu = (const ull*)ws;
    int base = blockIdx.x * 256;
    int p = t >> 1, h = t & 1;
    float* xs0 = xsbuf;
    float* xs1 = xsbuf + 256 * 17 + 1;
    ull a0[8], a1[8];
#pragma unroll
    for (int q8 = 0; q8 < 8; q8++) { a0[q8] = 0ull; a1[q8] = 0ull; }

    for (int it = 0; it < 4; it++) {
        __syncthreads();
        // stage chunk it (k 16it..) for half0 and chunk it+4 for half1
#pragma unroll
        for (int half = 0; half < 2; half++) {
            int kq0 = (half * 4 + it) * 4;
            float* dst = half ? xs1 : xs0;
#pragma unroll
            for (int j = 0; j < 4; j++) {
                int idx = j * 256 + t;
                int row = idx >> 2, q = idx & 3;
                int rg = base + row; if (rg >= NN) rg = NN - 1;
                float4 v = ((const float4*)x)[rg * 32 + kq0 + q];
                float* xr = dst + row * 17 + q * 4;
                xr[0] = v.x; xr[1] = v.y; xr[2] = v.z; xr[3] = v.w;
            }
        }
        __syncthreads();
        const float* myxs = h ? xs1 : xs0;
        int prow = (p * 2) * 17;
#pragma unroll
        for (int k = 0; k < 16; k++) {
            float xv0 = myxs[prow + k];
            float xv1 = myxs[prow + 17 + k];
            ull xx0, xx1;
            asm("mov.b64 %0, {%1, %1};" : "=l"(xx0) : "r"(__float_as_uint(xv0)));
            asm("mov.b64 %0, {%1, %1};" : "=l"(xx1) : "r"(__float_as_uint(xv1)));
            int kk = (h * 4 + it) * 16 + k;
            int wb = kk * 8 + h;          // ull index incl. bank gap
#pragma unroll
            for (int q8 = 0; q8 < 8; q8++) {
                ull wv = wsu[wb + q8];
                asm("fma.rn.f32x2 %0, %1, %2, %0;" : "+l"(a0[q8]) : "l"(xx0), "l"(wv));
                asm("fma.rn.f32x2 %0, %1, %2, %0;" : "+l"(a1[q8]) : "l"(xx1), "l"(wv));
            }
        }
    }
    // combine k-halves across lane pairs
#pragma unroll
    for (int q8 = 0; q8 < 8; q8++) {
        ull o0 = __shfl_xor_sync(0xFFFFFFFFu, a0[q8], 1);
        ull o1 = __shfl_xor_sync(0xFFFFFFFFu, a1[q8], 1);
        asm("add.rn.f32x2 %0, %0, %1;" : "+l"(a0[q8]) : "l"(o0));
        asm("add.rn.f32x2 %0, %0, %1;" : "+l"(a1[q8]) : "l"(o1));
    }
    if (h == 0) {
        int n0 = base + p * 2;
        if (n0 < NN) {
            ull* o = (ull*)(d_h0 + (size_t)n0 * HID);
#pragma unroll
            for (int q8 = 0; q8 < 8; q8++) o[q8] = a0[q8];
        }
        if (n0 + 1 < NN) {
            ull* o = (ull*)(d_h0 + (size_t)(n0 + 1) * HID);
#pragma unroll
            for (int q8 = 0; q8 < 8; q8++) o[q8] = a1[q8];
        }
    }
}

__global__ void kcount(const int* __restrict__ ei) {
    int e4 = blockIdx.x * blockDim.x + threadIdx.x;
    int4 d = ((const int4*)(ei + EE))[e4];
    atomicAdd(&d_cnt[d.x], 1);
    atomicAdd(&d_cnt[d.y], 1);
    atomicAdd(&d_cnt[d.z], 1);
    atomicAdd(&d_cnt[d.w], 1);
}

// ---- decoupled scan
__global__ void __launch_bounds__(SBLK) kscanA() {
    __shared__ int ws[32];
    int i = blockIdx.x * SBLK + threadIdx.x;
    int lane = threadIdx.x & 31, wd = threadIdx.x >> 5;
    int v = (i < NN) ? d_cnt[i] : 0;
    int s = v;
#pragma unroll
    for (int o = 16; o; o >>= 1) s += __shfl_xor_sync(0xFFFFFFFFu, s, o);
    if (lane == 0) ws[wd] = s;
    __syncthreads();
    if (wd == 0) {
        int s2 = ws[lane];
#pragma unroll
        for (int o = 16; o; o >>= 1) s2 += __shfl_xor_sync(0xFFFFFFFFu, s2, o);
        if (lane == 0) d_bsum[blockIdx.x] = s2;
    }
}

__global__ void kscanB() {
    __shared__ int sm[128];
    int t = threadIdx.x;
    int v = (t < NBLK) ? d_bsum[t] : 0;
    sm[t] = v;
    __syncthreads();
    for (int o = 1; o < 128; o <<= 1) {
        int y = (t >= o) ? sm[t - o] : 0;
        __syncthreads();
        sm[t] += y;
        __syncthreads();
    }
    if (t < NBLK) d_boff[t] = sm[t] - v;
    if (t == NBLK - 1) d_rowptr[NN] = sm[t];
}

__global__ void __launch_bounds__(SBLK) kscanC() {
    __shared__ int ws[32];
    int i = blockIdx.x * SBLK + threadIdx.x;
    int lane = threadIdx.x & 31, wd = threadIdx.x >> 5;
    int v = (i < NN) ? d_cnt[i] : 0;
    int xv = v;
#pragma unroll
    for (int o = 1; o < 32; o <<= 1) {
        int y = __shfl_up_sync(0xFFFFFFFFu, xv, o);
        if (lane >= o) xv += y;
    }
    if (lane == 31) ws[wd] = xv;
    __syncthreads();
    if (wd == 0) {
        int s2 = ws[lane];
#pragma unroll
        for (int o = 1; o < 32; o <<= 1) {
            int y = __shfl_up_sync(0xFFFFFFFFu, s2, o);
            if (lane >= o) s2 += y;
        }
        ws[lane] = s2;
    }
    __syncthreads();
    int excl = xv - v + (wd > 0 ? ws[wd - 1] : 0) + d_boff[blockIdx.x];
    if (i < NN) {
        d_rowptr[i] = excl;
        d_cursor[i] = excl;
        d_dinv[i] = rsqrt_acc((float)(v + 1));
        d_nidx[i] = -1;
    }
}

__global__ void kscatter(const int* __restrict__ ei) {
    int e4 = blockIdx.x * blockDim.x + threadIdx.x;
    int4 s = ((const int4*)ei)[e4];
    int4 d = ((const int4*)(ei + EE))[e4];
    d_csr[atomicAdd(&d_cursor[d.x], 1)] = s.x;
    d_csr[atomicAdd(&d_cursor[d.y], 1)] = s.y;
    d_csr[atomicAdd(&d_cursor[d.z], 1)] = s.z;
    d_csr[atomicAdd(&d_cursor[d.w], 1)] = s.w;
}

// conv1 (+relu) fp32 Kahan accumulation, 4-way unrolled; score linear terms
__global__ void kconv1(const float* __restrict__ b1, const float* __restrict__ pw1,
                       const float* __restrict__ pw2, const float* __restrict__ pb) {
    int gw = (blockIdx.x * blockDim.x + threadIdx.x) >> 5;
    if (gw >= NN) return;
    int lane = threadIdx.x & 31, half = lane >> 4, ch = lane & 15;
    int st = d_rowptr[gw], en = d_rowptr[gw + 1];
    float s0a = 0.f, c0a = 0.f, s1a = 0.f, c1a = 0.f;
    float s2a = 0.f, c2a = 0.f, s3a = 0.f, c3a = 0.f;
    int e = st + half;
    for (; e + 6 < en; e += 8) {
        int n0 = d_csr[e], n1 = d_csr[e + 2], n2 = d_csr[e + 4], n3 = d_csr[e + 6];
        kadd(s0a, c0a, d_dinv[n0] * d_h0[n0 * HID + ch]);
        kadd(s1a, c1a, d_dinv[n1] * d_h0[n1 * HID + ch]);
        kadd(s2a, c2a, d_dinv[n2] * d_h0[n2 * HID + ch]);
        kadd(s3a, c3a, d_dinv[n3] * d_h0[n3 * HID + ch]);
    }
    for (; e < en; e += 2) {
        int n0 = d_csr[e];
        kadd(s0a, c0a, d_dinv[n0] * d_h0[n0 * HID + ch]);
    }
    kadd(s0a, c0a, s1a); kadd(s0a, c0a, -c1a);
    kadd(s0a, c0a, s2a); kadd(s0a, c0a, -c2a);
    kadd(s0a, c0a, s3a); kadd(s0a, c0a, -c3a);
    float os = __shfl_xor_sync(0xFFFFFFFFu, s0a, 16);
    float oc = __shfl_xor_sync(0xFFFFFFFFu, c0a, 16);
    kadd(s0a, c0a, os); kadd(s0a, c0a, -oc);
    float a = s0a - c0a;
    float degf = (float)(en - st + 1);
    float hv = d_dinv[gw] * a + d_h0[gw * HID + ch] / degf + b1[ch];
    hv = fmaxf(hv, 0.f);
    if (half == 0) d_h[gw * HID + ch] = hv;
    float u1 = hv * pw1[ch];
    float u2 = hv * pw2[ch];
#pragma unroll
    for (int o = 8; o; o >>= 1) {
        u1 += __shfl_xor_sync(0xFFFFFFFFu, u1, o);
        u2 += __shfl_xor_sync(0xFFFFFFFFu, u2, o);
    }
    if (lane == 0) { d_spart[gw] = u1 + pb[0]; d_t2[gw] = u2; }
}

// score = spart + sum_{in-neighbors} t2 (Kahan); build sort key
__global__ void kpool() {
    int gw = (blockIdx.x * blockDim.x + threadIdx.x) >> 5;
    if (gw >= NN) return;
    int lane = threadIdx.x & 31;
    int st = d_rowptr[gw], en = d_rowptr[gw + 1];
    float sum = 0.f, comp = 0.f;
    for (int e = st + lane; e < en; e += 32) kadd(sum, comp, d_t2[d_csr[e]]);
#pragma unroll
    for (int o = 16; o; o >>= 1) {
        float os = __shfl_xor_sync(0xFFFFFFFFu, sum, o);
        float oc = __shfl_xor_sync(0xFFFFFFFFu, comp, o);
        kadd(sum, comp, os); kadd(sum, comp, -oc);
    }
    if (lane == 0) {
        float sv = d_spart[gw] + (sum - comp);
        d_s[gw] = sv;
        unsigned u = __float_as_uint(sv);
        u = (u & 0x80000000u) ? ~u : (u | 0x80000000u);
        d_keys[gw] = ((ull)u << 32) | (ull)(~(unsigned)gw);
    }
}

// bitonic sort, descending, SSIZE unique keys
__global__ void __launch_bounds__(1024) ksort_init() {
    __shared__ ull sk[TILE];
    int base = blockIdx.x * TILE;
    for (int i = threadIdx.x; i < TILE; i += 1024) sk[i] = d_keys[base + i];
    __syncthreads();
    for (int k = 2; k <= TILE; k <<= 1)
        for (int j = k >> 1; j > 0; j >>= 1) {
            for (int i = threadIdx.x; i < TILE; i += 1024) {
                int p = i ^ j;
                if (p > i) {
                    bool desc = (((base + i) & k) == 0);
                    ull A = sk[i], B = sk[p];
                    if ((A < B) == desc) { sk[i] = B; sk[p] = A; }
                }
            }
            __syncthreads();
        }
    for (int i = threadIdx.x; i < TILE; i += 1024) d_keys[base + i] = sk[i];
}

// all global steps (j >= 4096) of phase k, fused.
__global__ void __launch_bounds__(1024) kcol(int k) {
    __shared__ ull sk[4096];          // [m][low] : 32 x 128
    int lowbase = blockIdx.x * 128;
    for (int idx = threadIdx.x; idx < 4096; idx += 1024) {
        int m = idx >> 7, low = idx & 127;
        sk[idx] = d_keys[m * 4096 + lowbase + low];
    }
    __syncthreads();
    int kp = k >> 12;                 // k' in units of 4096
    for (int jp = kp >> 1; jp >= 1; jp >>= 1) {
        for (int q = threadIdx.x; q < 2048; q += 1024) {
            int low = q & 127;
            int mg = q >> 7;          // 0..15
            int m = ((mg & ~(jp - 1)) << 1) | (mg & (jp - 1));
            int p = m | jp;
            bool desc = ((m & kp) == 0);
            ull A = sk[m * 128 + low], B = sk[p * 128 + low];
            if ((A < B) == desc) { sk[m * 128 + low] = B; sk[p * 128 + low] = A; }
        }
        __syncthreads();
    }
    for (int idx = threadIdx.x; idx < 4096; idx += 1024) {
        int m = idx >> 7, low = idx & 127;
        d_keys[m * 4096 + lowbase + low] = sk[idx];
    }
}

__global__ void __launch_bounds__(1024) ksort_merge(int k) {
    __shared__ ull sk[TILE];
    int base = blockIdx.x * TILE;
    for (int i = threadIdx.x; i < TILE; i += 1024) sk[i] = d_keys[base + i];
    __syncthreads();
    for (int j = TILE >> 1; j > 0; j >>= 1) {
        for (int i = threadIdx.x; i < TILE; i += 1024) {
            int p = i ^ j;
            if (p > i) {
                bool desc = (((base + i) & k) == 0);
                ull A = sk[i], B = sk[p];
                if ((A < B) == desc) { sk[i] = B; sk[p] = A; }
            }
        }
        __syncthreads();
    }
    for (int i = threadIdx.x; i < TILE; i += 1024) d_keys[base + i] = sk[i];
}

// top-K select: perm, inverse map, h2v[orig id] = tanh(s) * (h @ w2)
__global__ void kselect(const float* __restrict__ w2) {
    int r = (blockIdx.x * blockDim.x + threadIdx.x) >> 5;
    if (r >= KK) return;
    int lane = threadIdx.x & 31;
    ull key = d_keys[r];
    int idx = (int)(~(unsigned)(key & 0xFFFFFFFFull));
    if (lane == 0) { d_nidx[idx] = r; d_perm[r] = idx; }
    if (lane < NCLS) {
        float th = tanhf(d_s[idx]);
        float acc = 0.f;
#pragma unroll
        for (int j = 0; j < HID; j++)
            acc += d_h[idx * HID + j] * w2[j * NCLS + lane];
        ((float*)d_h2v)[idx * 12 + lane] = th * acc;
    }
}

// surviving-degree of kept nodes; pre-scale h2v rows by dinv2
__global__ void kdeg2() {
    int r = (blockIdx.x * blockDim.x + threadIdx.x) >> 5;
    if (r >= KK) return;
    int lane = threadIdx.x & 31;
    int i = d_perm[r];
    int st = d_rowptr[i], en = d_rowptr[i + 1];
    int cnt = 0;
    for (int e = st + lane; e < en; e += 32) cnt += (d_nidx[d_csr[e]] >= 0);
#pragma unroll
    for (int o = 16; o; o >>= 1) cnt += __shfl_xor_sync(0xFFFFFFFFu, cnt, o);
    float d2 = rsqrt_acc((float)(cnt + 1));
    if (lane == 0) d_dinv2[r] = d2;
    if (lane < 12) ((float*)d_h2v)[i * 12 + lane] *= d2;
}

// conv2: branch-free float4 gathers from dense h2v + relu + log_softmax
__global__ void kconv2(const float* __restrict__ b2, float* __restrict__ out) {
    __shared__ __align__(16) float red[8][12];
    int r = (blockIdx.x * blockDim.x + threadIdx.x) >> 5;
    if (r >= KK) return;
    int lane = threadIdx.x & 31, wip = (threadIdx.x >> 5) & 7;
    int i = d_perm[r];
    int st = d_rowptr[i], en = d_rowptr[i + 1];
    const float* h2vf = (const float*)d_h2v;
    float4 a0 = {0,0,0,0}, a1 = {0,0,0,0}, a2 = {0,0,0,0};
    for (int e = st + lane; e < en; e += 32) {
        int n = d_csr[e];
        const float4* row = (const float4*)(h2vf + n * 12);
        float4 v0 = row[0], v1 = row[1], v2 = row[2];
        a0.x += v0.x; a0.y += v0.y; a0.z += v0.z; a0.w += v0.w;
        a1.x += v1.x; a1.y += v1.y; a1.z += v1.z; a1.w += v1.w;
        a2.x += v2.x; a2.y += v2.y; a2.z += v2.z; a2.w += v2.w;
    }
#pragma unroll
    for (int o = 16; o; o >>= 1) {
        a0.x += __shfl_xor_sync(0xFFFFFFFFu, a0.x, o);
        a0.y += __shfl_xor_sync(0xFFFFFFFFu, a0.y, o);
        a0.z += __shfl_xor_sync(0xFFFFFFFFu, a0.z, o);
        a0.w += __shfl_xor_sync(0xFFFFFFFFu, a0.w, o);
        a1.x += __shfl_xor_sync(0xFFFFFFFFu, a1.x, o);
        a1.y += __shfl_xor_sync(0xFFFFFFFFu, a1.y, o);
        a1.z += __shfl_xor_sync(0xFFFFFFFFu, a1.z, o);
        a1.w += __shfl_xor_sync(0xFFFFFFFFu, a1.w, o);
        a2.x += __shfl_xor_sync(0xFFFFFFFFu, a2.x, o);
        a2.y += __shfl_xor_sync(0xFFFFFFFFu, a2.y, o);
    }
    if (lane == 0) {
        ((float4*)red[wip])[0] = a0;
        ((float4*)red[wip])[1] = a1;
        ((float4*)red[wip])[2] = a2;
    }
    __syncwarp();
    bool act = lane < NCLS;
    float own = act ? h2vf[i * 12 + lane] : 0.f;
    float v = act
        ? fmaxf(d_dinv2[r] * (red[wip][lane] + own) + b2[lane], 0.f)
        : -1e30f;
    float m = v;
#pragma unroll
    for (int o = 8; o; o >>= 1)
        m = fmaxf(m, __shfl_xor_sync(0xFFFFFFFFu, m, o, 16));
    float ex = act ? expf(v - m) : 0.f;
#pragma unroll
    for (int o = 8; o; o >>= 1)
        ex += __shfl_xor_sync(0xFFFFFFFFu, ex, o, 16);
    if (act) out[r * NCLS + lane] = v - m - logf(ex);
}

extern "C" void kernel_launch(void* const* d_in, const int* in_sizes, int n_in,
                              void* d_out, int out_size) {
    const float* x  = (const float*)d_in[0];
    const int*   ei = (const int*)d_in[1];
    const float* w1 = (const float*)d_in[2];
    const float* b1 = (const float*)d_in[3];
    const float* pw1 = (const float*)d_in[4];
    const float* pw2 = (const float*)d_in[5];
    const float* pb = (const float*)d_in[6];
    const float* w2 = (const float*)d_in[7];
    const float* b2 = (const float*)d_in[8];
    float* out = (float*)d_out;

    kinit<<<(NN * 3 + 255) / 256, 256>>>();
    kcount<<<EE / 1024, 256>>>(ei);
    kscanA<<<NBLK, SBLK>>>();
    kgemm1<<<(NN + 255) / 256, 256>>>(x, w1);   // slot 4: gets profiled
    kscanB<<<1, 128>>>();
    kscanC<<<NBLK, SBLK>>>();
    kscatter<<<EE / 1024, 256>>>(ei);
    kconv1<<<NN * 32 / 256, 256>>>(b1, pw1, pw2, pb);
    kpool<<<NN * 32 / 256, 256>>>();

    ksort_init<<<SSIZE / TILE, 1024>>>();
    for (int k = TILE * 2; k <= SSIZE; k <<= 1) {
        kcol<<<SSIZE / 4096, 1024>>>(k);
        ksort_merge<<<SSIZE / TILE, 1024>>>(k);
    }

    kselect<<<KK * 32 / 256, 256>>>(w2);
    kdeg2<<<KK * 32 / 256, 256>>>();
    kconv2<<<KK * 32 / 256, 256>>>(b2, out);
}

// round 11
// speedup vs baseline: 1.0846x; 1.0064x over previous
#include <cuda_runtime.h>
#include <math.h>

#define NN 100000
#define EE 3200000
#define HID 16
#define NCLS 10
#define KK 50000
#define SSIZE 131072
#define TILE 4096
#define SBLK 1024
#define NBLK 98   // ceil(100000/1024)

typedef unsigned long long ull;

__device__ float  d_h0[NN * HID];
__device__ float  d_h[NN * HID];
__device__ int    d_cnt[NN];          // zero at load; scanC re-zeroes each exec
__device__ int    d_rowptr[NN + 1];
__device__ int    d_cursor[NN];
__device__ float  d_dinv[NN];
__device__ int    d_csr[EE];
__device__ float  d_spart[NN];
__device__ float  d_t2[NN];
__device__ float  d_s[NN];
__device__ ull    d_keys[SSIZE];      // zero at load; sort permutes zero tail in place
__device__ int    d_nidx[NN];
__device__ int    d_perm[KK];
__device__ float4 d_h2v[NN * 3];      // 12 floats per ORIGINAL node id; dropped rows stay 0
__device__ float  d_dinv2[KK];
__device__ int    d_bsum[NBLK];

// Kahan compensated add (safe under FMA contraction: no mul inside)
__device__ __forceinline__ void kadd(float& s, float& c, float v) {
    float y = v - c;
    float t = s + y;
    c = (t - s) - y;
    s = t;
}

// accurate fp32 rsqrt: hardware approx + one Newton step
__device__ __forceinline__ float rsqrt_acc(float x) {
    float r = rsqrtf(x);
    return r * (1.5f - 0.5f * x * r * r);
}

// h0 = x @ w1 : f32x2 packed FMA, 2 nodes x 16ch per thread, split-k over
// lane pairs (h = t&1 owns k-half h).
__global__ void __launch_bounds__(256) kgemm1(const float* __restrict__ x,
                                              const float* __restrict__ w1) {
    __shared__ __align__(16) float xsbuf[2 * (256 * 17) + 1];
    __shared__ __align__(16) float ws[2050];
    int t = threadIdx.x;
    for (int f = t; f < 2048; f += 256) {
        int kk = f >> 4;
        ws[f + ((kk >= 64) ? 2 : 0)] = w1[f];
    }
    const ull* wsu = (const ull*)ws;
    int base = blockIdx.x * 256;
    int p = t >> 1, h = t & 1;
    float* xs0 = xsbuf;
    float* xs1 = xsbuf + 256 * 17 + 1;
    ull a0[8], a1[8];
#pragma unroll
    for (int q8 = 0; q8 < 8; q8++) { a0[q8] = 0ull; a1[q8] = 0ull; }

    for (int it = 0; it < 4; it++) {
        __syncthreads();
#pragma unroll
        for (int half = 0; half < 2; half++) {
            int kq0 = (half * 4 + it) * 4;
            float* dst = half ? xs1 : xs0;
#pragma unroll
            for (int j = 0; j < 4; j++) {
                int idx = j * 256 + t;
                int row = idx >> 2, q = idx & 3;
                int rg = base + row; if (rg >= NN) rg = NN - 1;
                float4 v = ((const float4*)x)[rg * 32 + kq0 + q];
                float* xr = dst + row * 17 + q * 4;
                xr[0] = v.x; xr[1] = v.y; xr[2] = v.z; xr[3] = v.w;
            }
        }
        __syncthreads();
        const float* myxs = h ? xs1 : xs0;
        int prow = (p * 2) * 17;
#pragma unroll
        for (int k = 0; k < 16; k++) {
            float xv0 = myxs[prow + k];
            float xv1 = myxs[prow + 17 + k];
            ull xx0, xx1;
            asm("mov.b64 %0, {%1, %1};" : "=l"(xx0) : "r"(__float_as_uint(xv0)));
            asm("mov.b64 %0, {%1, %1};" : "=l"(xx1) : "r"(__float_as_uint(xv1)));
            int kk = (h * 4 + it) * 16 + k;
            int wb = kk * 8 + h;
#pragma unroll
            for (int q8 = 0; q8 < 8; q8++) {
                ull wv = wsu[wb + q8];
                asm("fma.rn.f32x2 %0, %1, %2, %0;" : "+l"(a0[q8]) : "l"(xx0), "l"(wv));
                asm("fma.rn.f32x2 %0, %1, %2, %0;" : "+l"(a1[q8]) : "l"(xx1), "l"(wv));
            }
        }
    }
#pragma unroll
    for (int q8 = 0; q8 < 8; q8++) {
        ull o0 = __shfl_xor_sync(0xFFFFFFFFu, a0[q8], 1);
        ull o1 = __shfl_xor_sync(0xFFFFFFFFu, a1[q8], 1);
        asm("add.rn.f32x2 %0, %0, %1;" : "+l"(a0[q8]) : "l"(o0));
        asm("add.rn.f32x2 %0, %0, %1;" : "+l"(a1[q8]) : "l"(o1));
    }
    if (h == 0) {
        int n0 = base + p * 2;
        if (n0 < NN) {
            ull* o = (ull*)(d_h0 + (size_t)n0 * HID);
#pragma unroll
            for (int q8 = 0; q8 < 8; q8++) o[q8] = a0[q8];
        }
        if (n0 + 1 < NN) {
            ull* o = (ull*)(d_h0 + (size_t)(n0 + 1) * HID);
#pragma unroll
            for (int q8 = 0; q8 < 8; q8++) o[q8] = a1[q8];
        }
    }
}

__global__ void kcount(const int* __restrict__ ei) {
    int e4 = blockIdx.x * blockDim.x + threadIdx.x;
    int4 d = ((const int4*)(ei + EE))[e4];
    atomicAdd(&d_cnt[d.x], 1);
    atomicAdd(&d_cnt[d.y], 1);
    atomicAdd(&d_cnt[d.z], 1);
    atomicAdd(&d_cnt[d.w], 1);
}

// block sums of cnt
__global__ void __launch_bounds__(SBLK) kscanA() {
    __shared__ int ws[32];
    int i = blockIdx.x * SBLK + threadIdx.x;
    int lane = threadIdx.x & 31, wd = threadIdx.x >> 5;
    int v = (i < NN) ? d_cnt[i] : 0;
    int s = v;
#pragma unroll
    for (int o = 16; o; o >>= 1) s += __shfl_xor_sync(0xFFFFFFFFu, s, o);
    if (lane == 0) ws[wd] = s;
    __syncthreads();
    if (wd == 0) {
        int s2 = ws[lane];
#pragma unroll
        for (int o = 16; o; o >>= 1) s2 += __shfl_xor_sync(0xFFFFFFFFu, s2, o);
        if (lane == 0) d_bsum[blockIdx.x] = s2;
    }
}

// fused: per-block offset from bsum + local exclusive scan + derived arrays;
// re-zeroes cnt for the next execution.
__global__ void __launch_bounds__(SBLK) kscanC() {
    __shared__ int ws[32];
    __shared__ int off_s;
    int bid = blockIdx.x;
    int t = threadIdx.x, lane = t & 31, wd = t >> 5;
    if (wd == 0) {
        int acc = 0;
        for (int b = lane; b < bid; b += 32) acc += d_bsum[b];
#pragma unroll
        for (int o = 16; o; o >>= 1) acc += __shfl_xor_sync(0xFFFFFFFFu, acc, o);
        if (lane == 0) {
            off_s = acc;
            if (bid == NBLK - 1) d_rowptr[NN] = acc + d_bsum[NBLK - 1];
        }
    }
    int i = bid * SBLK + t;
    int v = (i < NN) ? d_cnt[i] : 0;
    int xv = v;
#pragma unroll
    for (int o = 1; o < 32; o <<= 1) {
        int y = __shfl_up_sync(0xFFFFFFFFu, xv, o);
        if (lane >= o) xv += y;
    }
    if (lane == 31) ws[wd] = xv;
    __syncthreads();
    if (wd == 0) {
        int s2 = ws[lane];
#pragma unroll
        for (int o = 1; o < 32; o <<= 1) {
            int y = __shfl_up_sync(0xFFFFFFFFu, s2, o);
            if (lane >= o) s2 += y;
        }
        ws[lane] = s2;
    }
    __syncthreads();
    int excl = xv - v + (wd > 0 ? ws[wd - 1] : 0) + off_s;
    if (i < NN) {
        d_rowptr[i] = excl;
        d_cursor[i] = excl;
        d_dinv[i] = rsqrt_acc((float)(v + 1));
        d_nidx[i] = -1;
        d_cnt[i] = 0;      // restore invariant for next execution
    }
}

__global__ void kscatter(const int* __restrict__ ei) {
    int e4 = blockIdx.x * blockDim.x + threadIdx.x;
    int4 s = ((const int4*)ei)[e4];
    int4 d = ((const int4*)(ei + EE))[e4];
    d_csr[atomicAdd(&d_cursor[d.x], 1)] = s.x;
    d_csr[atomicAdd(&d_cursor[d.y], 1)] = s.y;
    d_csr[atomicAdd(&d_cursor[d.z], 1)] = s.z;
    d_csr[atomicAdd(&d_cursor[d.w], 1)] = s.w;
}

// conv1 (+relu) fp32 Kahan accumulation, 4-way unrolled; score linear terms
__global__ void kconv1(const float* __restrict__ b1, const float* __restrict__ pw1,
                       const float* __restrict__ pw2, const float* __restrict__ pb) {
    int gw = (blockIdx.x * blockDim.x + threadIdx.x) >> 5;
    if (gw >= NN) return;
    int lane = threadIdx.x & 31, half = lane >> 4, ch = lane & 15;
    int st = d_rowptr[gw], en = d_rowptr[gw + 1];
    float s0a = 0.f, c0a = 0.f, s1a = 0.f, c1a = 0.f;
    float s2a = 0.f, c2a = 0.f, s3a = 0.f, c3a = 0.f;
    int e = st + half;
    for (; e + 6 < en; e += 8) {
        int n0 = d_csr[e], n1 = d_csr[e + 2], n2 = d_csr[e + 4], n3 = d_csr[e + 6];
        kadd(s0a, c0a, d_dinv[n0] * d_h0[n0 * HID + ch]);
        kadd(s1a, c1a, d_dinv[n1] * d_h0[n1 * HID + ch]);
        kadd(s2a, c2a, d_dinv[n2] * d_h0[n2 * HID + ch]);
        kadd(s3a, c3a, d_dinv[n3] * d_h0[n3 * HID + ch]);
    }
    for (; e < en; e += 2) {
        int n0 = d_csr[e];
        kadd(s0a, c0a, d_dinv[n0] * d_h0[n0 * HID + ch]);
    }
    kadd(s0a, c0a, s1a); kadd(s0a, c0a, -c1a);
    kadd(s0a, c0a, s2a); kadd(s0a, c0a, -c2a);
    kadd(s0a, c0a, s3a); kadd(s0a, c0a, -c3a);
    float os = __shfl_xor_sync(0xFFFFFFFFu, s0a, 16);
    float oc = __shfl_xor_sync(0xFFFFFFFFu, c0a, 16);
    kadd(s0a, c0a, os); kadd(s0a, c0a, -oc);
    float a = s0a - c0a;
    float degf = (float)(en - st + 1);
    float hv = d_dinv[gw] * a + d_h0[gw * HID + ch] / degf + b1[ch];
    hv = fmaxf(hv, 0.f);
    if (half == 0) d_h[gw * HID + ch] = hv;
    float u1 = hv * pw1[ch];
    float u2 = hv * pw2[ch];
#pragma unroll
    for (int o = 8; o; o >>= 1) {
        u1 += __shfl_xor_sync(0xFFFFFFFFu, u1, o);
        u2 += __shfl_xor_sync(0xFFFFFFFFu, u2, o);
    }
    if (lane == 0) { d_spart[gw] = u1 + pb[0]; d_t2[gw] = u2; }
}

// score = spart + sum_{in-neighbors} t2 (Kahan); build sort key
__global__ void kpool() {
    int gw = (blockIdx.x * blockDim.x + threadIdx.x) >> 5;
    if (gw >= NN) return;
    int lane = threadIdx.x & 31;
    int st = d_rowptr[gw], en = d_rowptr[gw + 1];
    float sum = 0.f, comp = 0.f;
    for (int e = st + lane; e < en; e += 32) kadd(sum, comp, d_t2[d_csr[e]]);
#pragma unroll
    for (int o = 16; o; o >>= 1) {
        float os = __shfl_xor_sync(0xFFFFFFFFu, sum, o);
        float oc = __shfl_xor_sync(0xFFFFFFFFu, comp, o);
        kadd(sum, comp, os); kadd(sum, comp, -oc);
    }
    if (lane == 0) {
        float sv = d_spart[gw] + (sum - comp);
        d_s[gw] = sv;
        unsigned u = __float_as_uint(sv);
        u = (u & 0x80000000u) ? ~u : (u | 0x80000000u);
        d_keys[gw] = ((ull)u << 32) | (ull)(~(unsigned)gw);
    }
}

// bitonic sort, descending, SSIZE keys (tail = all-zero padding keys)
__global__ void __launch_bounds__(1024) ksort_init() {
    __shared__ ull sk[TILE];
    int base = blockIdx.x * TILE;
    for (int i = threadIdx.x; i < TILE; i += 1024) sk[i] = d_keys[base + i];
    __syncthreads();
    for (int k = 2; k <= TILE; k <<= 1)
        for (int j = k >> 1; j > 0; j >>= 1) {
            for (int i = threadIdx.x; i < TILE; i += 1024) {
                int p = i ^ j;
                if (p > i) {
                    bool desc = (((base + i) & k) == 0);
                    ull A = sk[i], B = sk[p];
                    if ((A < B) == desc) { sk[i] = B; sk[p] = A; }
                }
            }
            __syncthreads();
        }
    for (int i = threadIdx.x; i < TILE; i += 1024) d_keys[base + i] = sk[i];
}

// all global steps (j >= 4096) of phase k, fused.
__global__ void __launch_bounds__(1024) kcol(int k) {
    __shared__ ull sk[4096];          // [m][low] : 32 x 128
    int lowbase = blockIdx.x * 128;
    for (int idx = threadIdx.x; idx < 4096; idx += 1024) {
        int m = idx >> 7, low = idx & 127;
        sk[idx] = d_keys[m * 4096 + lowbase + low];
    }
    __syncthreads();
    int kp = k >> 12;                 // k' in units of 4096
    for (int jp = kp >> 1; jp >= 1; jp >>= 1) {
        for (int q = threadIdx.x; q < 2048; q += 1024) {
            int low = q & 127;
            int mg = q >> 7;          // 0..15
            int m = ((mg & ~(jp - 1)) << 1) | (mg & (jp - 1));
            int p = m | jp;
            bool desc = ((m & kp) == 0);
            ull A = sk[m * 128 + low], B = sk[p * 128 + low];
            if ((A < B) == desc) { sk[m * 128 + low] = B; sk[p * 128 + low] = A; }
        }
        __syncthreads();
    }
    for (int idx = threadIdx.x; idx < 4096; idx += 1024) {
        int m = idx >> 7, low = idx & 127;
        d_keys[m * 4096 + lowbase + low] = sk[idx];
    }
}

__global__ void __launch_bounds__(1024) ksort_merge(int k) {
    __shared__ ull sk[TILE];
    int base = blockIdx.x * TILE;
    for (int i = threadIdx.x; i < TILE; i += 1024) sk[i] = d_keys[base + i];
    __syncthreads();
    for (int j = TILE >> 1; j > 0; j >>= 1) {
        for (int i = threadIdx.x; i < TILE; i += 1024) {
            int p = i ^ j;
            if (p > i) {
                bool desc = (((base + i) & k) == 0);
                ull A = sk[i], B = sk[p];
                if ((A < B) == desc) { sk[i] = B; sk[p] = A; }
            }
        }
        __syncthreads();
    }
    for (int i = threadIdx.x; i < TILE; i += 1024) d_keys[base + i] = sk[i];
}

// top-K select: perm, inverse map, h2v[orig id] = tanh(s) * (h @ w2)
__global__ void kselect(const float* __restrict__ w2) {
    int r = (blockIdx.x * blockDim.x + threadIdx.x) >> 5;
    if (r >= KK) return;
    int lane = threadIdx.x & 31;
    ull key = d_keys[r];
    int idx = (int)(~(unsigned)(key & 0xFFFFFFFFull));
    if (lane == 0) { d_nidx[idx] = r; d_perm[r] = idx; }
    if (lane < NCLS) {
        float th = tanhf(d_s[idx]);
        float acc = 0.f;
#pragma unroll
        for (int j = 0; j < HID; j++)
            acc += d_h[idx * HID + j] * w2[j * NCLS + lane];
        ((float*)d_h2v)[idx * 12 + lane] = th * acc;
    }
}

// surviving-degree of kept nodes; pre-scale h2v rows by dinv2
__global__ void kdeg2() {
    int r = (blockIdx.x * blockDim.x + threadIdx.x) >> 5;
    if (r >= KK) return;
    int lane = threadIdx.x & 31;
    int i = d_perm[r];
    int st = d_rowptr[i], en = d_rowptr[i + 1];
    int cnt = 0;
    for (int e = st + lane; e < en; e += 32) cnt += (d_nidx[d_csr[e]] >= 0);
#pragma unroll
    for (int o = 16; o; o >>= 1) cnt += __shfl_xor_sync(0xFFFFFFFFu, cnt, o);
    float d2 = rsqrt_acc((float)(cnt + 1));
    if (lane == 0) d_dinv2[r] = d2;
    if (lane < 12) ((float*)d_h2v)[i * 12 + lane] *= d2;
}

// conv2: branch-free float4 gathers from dense h2v + relu + log_softmax
__global__ void kconv2(const float* __restrict__ b2, float* __restrict__ out) {
    __shared__ __align__(16) float red[8][12];
    int r = (blockIdx.x * blockDim.x + threadIdx.x) >> 5;
    if (r >= KK) return;
    int lane = threadIdx.x & 31, wip = (threadIdx.x >> 5) & 7;
    int i = d_perm[r];
    int st = d_rowptr[i], en = d_rowptr[i + 1];
    const float* h2vf = (const float*)d_h2v;
    float4 a0 = {0,0,0,0}, a1 = {0,0,0,0}, a2 = {0,0,0,0};
    for (int e = st + lane; e < en; e += 32) {
        int n = d_csr[e];
        const float4* row = (const float4*)(h2vf + n * 12);
        float4 v0 = row[0], v1 = row[1], v2 = row[2];
        a0.x += v0.x; a0.y += v0.y; a0.z += v0.z; a0.w += v0.w;
        a1.x += v1.x; a1.y += v1.y; a1.z += v1.z; a1.w += v1.w;
        a2.x += v2.x; a2.y += v2.y; a2.z += v2.z; a2.w += v2.w;
    }
#pragma unroll
    for (int o = 16; o; o >>= 1) {
        a0.x += __shfl_xor_sync(0xFFFFFFFFu, a0.x, o);
        a0.y += __shfl_xor_sync(0xFFFFFFFFu, a0.y, o);
        a0.z += __shfl_xor_sync(0xFFFFFFFFu, a0.z, o);
        a0.w += __shfl_xor_sync(0xFFFFFFFFu, a0.w, o);
        a1.x += __shfl_xor_sync(0xFFFFFFFFu, a1.x, o);
        a1.y += __shfl_xor_sync(0xFFFFFFFFu, a1.y, o);
        a1.z += __shfl_xor_sync(0xFFFFFFFFu, a1.z, o);
        a1.w += __shfl_xor_sync(0xFFFFFFFFu, a1.w, o);
        a2.x += __shfl_xor_sync(0xFFFFFFFFu, a2.x, o);
        a2.y += __shfl_xor_sync(0xFFFFFFFFu, a2.y, o);
    }
    if (lane == 0) {
        ((float4*)red[wip])[0] = a0;
        ((float4*)red[wip])[1] = a1;
        ((float4*)red[wip])[2] = a2;
    }
    __syncwarp();
    bool act = lane < NCLS;
    float own = act ? h2vf[i * 12 + lane] : 0.f;
    float v = act
        ? fmaxf(d_dinv2[r] * (red[wip][lane] + own) + b2[lane], 0.f)
        : -1e30f;
    float m = v;
#pragma unroll
    for (int o = 8; o; o >>= 1)
        m = fmaxf(m, __shfl_xor_sync(0xFFFFFFFFu, m, o, 16));
    float ex = act ? expf(v - m) : 0.f;
#pragma unroll
    for (int o = 8; o; o >>= 1)
        ex += __shfl_xor_sync(0xFFFFFFFFu, ex, o, 16);
    if (act) out[r * NCLS + lane] = v - m - logf(ex);
}

extern "C" void kernel_launch(void* const* d_in, const int* in_sizes, int n_in,
                              void* d_out, int out_size) {
    const float* x  = (const float*)d_in[0];
    const int*   ei = (const int*)d_in[1];
    const float* w1 = (const float*)d_in[2];
    const float* b1 = (const float*)d_in[3];
    const float* pw1 = (const float*)d_in[4];
    const float* pw2 = (const float*)d_in[5];
    const float* pb = (const float*)d_in[6];
    const float* w2 = (const float*)d_in[7];
    const float* b2 = (const float*)d_in[8];
    float* out = (float*)d_out;

    kcount<<<EE / 1024, 256>>>(ei);
    kscanA<<<NBLK, SBLK>>>();
    kscanC<<<NBLK, SBLK>>>();
    kscatter<<<EE / 1024, 256>>>(ei);           // slot 4: gets profiled
    kgemm1<<<(NN + 255) / 256, 256>>>(x, w1);
    kconv1<<<NN * 32 / 256, 256>>>(b1, pw1, pw2, pb);
    kpool<<<NN * 32 / 256, 256>>>();

    ksort_init<<<SSIZE / TILE, 1024>>>();
    for (int k = TILE * 2; k <= SSIZE; k <<= 1) {
        kcol<<<SSIZE / 4096, 1024>>>(k);
        ksort_merge<<<SSIZE / TILE, 1024>>>(k);
    }

    kselect<<<KK * 32 / 256, 256>>>(w2);
    kdeg2<<<KK * 32 / 256, 256>>>();
    kconv2<<<KK * 32 / 256, 256>>>(b2, out);
}

// round 12
// speedup vs baseline: 1.0892x; 1.0042x over previous
#include <cuda_runtime.h>
#include <math.h>

#define NN 100000
#define EE 3200000
#define HID 16
#define NCLS 10
#define KK 50000
#define SSIZE 131072
#define TILE 4096
#define SBLK 1024
#define NBLK 98   // ceil(100000/1024)

typedef unsigned long long ull;

__device__ float  d_h0[NN * HID];
__device__ float  d_h[NN * HID];
__device__ int    d_cnt[NN];          // zero at load; scanC re-zeroes each exec
__device__ int    d_rowptr[NN + 1];
__device__ float  d_dinv[NN];
__device__ int    d_csr[EE];
__device__ int    d_rank[EE];         // edge's arrival rank within its dst bucket
__device__ float  d_spart[NN];
__device__ float  d_t2[NN];
__device__ float  d_s[NN];
__device__ ull    d_keys[SSIZE];      // zero at load; sort permutes zero tail in place
__device__ int    d_nidx[NN];
__device__ int    d_perm[KK];
__device__ float4 d_h2v[NN * 3];      // 12 floats per ORIGINAL node id; dropped rows stay 0
__device__ float  d_dinv2[KK];
__device__ int    d_bsum[NBLK];

// Kahan compensated add (safe under FMA contraction: no mul inside)
__device__ __forceinline__ void kadd(float& s, float& c, float v) {
    float y = v - c;
    float t = s + y;
    c = (t - s) - y;
    s = t;
}

// accurate fp32 rsqrt: hardware approx + one Newton step
__device__ __forceinline__ float rsqrt_acc(float x) {
    float r = rsqrtf(x);
    return r * (1.5f - 0.5f * x * r * r);
}

// h0 = x @ w1 : f32x2 packed FMA, 2 nodes x 16ch per thread, split-k over
// lane pairs (h = t&1 owns k-half h).
__global__ void __launch_bounds__(256) kgemm1(const float* __restrict__ x,
                                              const float* __restrict__ w1) {
    __shared__ __align__(16) float xsbuf[2 * (256 * 17) + 1];
    __shared__ __align__(16) float ws[2050];
    int t = threadIdx.x;
    for (int f = t; f < 2048; f += 256) {
        int kk = f >> 4;
        ws[f + ((kk >= 64) ? 2 : 0)] = w1[f];
    }
    const ull* wsu = (const ull*)ws;
    int base = blockIdx.x * 256;
    int p = t >> 1, h = t & 1;
    float* xs0 = xsbuf;
    float* xs1 = xsbuf + 256 * 17 + 1;
    ull a0[8], a1[8];
#pragma unroll
    for (int q8 = 0; q8 < 8; q8++) { a0[q8] = 0ull; a1[q8] = 0ull; }

    for (int it = 0; it < 4; it++) {
        __syncthreads();
#pragma unroll
        for (int half = 0; half < 2; half++) {
            int kq0 = (half * 4 + it) * 4;
            float* dst = half ? xs1 : xs0;
#pragma unroll
            for (int j = 0; j < 4; j++) {
                int idx = j * 256 + t;
                int row = idx >> 2, q = idx & 3;
                int rg = base + row; if (rg >= NN) rg = NN - 1;
                float4 v = ((const float4*)x)[rg * 32 + kq0 + q];
                float* xr = dst + row * 17 + q * 4;
                xr[0] = v.x; xr[1] = v.y; xr[2] = v.z; xr[3] = v.w;
            }
        }
        __syncthreads();
        const float* myxs = h ? xs1 : xs0;
        int prow = (p * 2) * 17;
#pragma unroll
        for (int k = 0; k < 16; k++) {
            float xv0 = myxs[prow + k];
            float xv1 = myxs[prow + 17 + k];
            ull xx0, xx1;
            asm("mov.b64 %0, {%1, %1};" : "=l"(xx0) : "r"(__float_as_uint(xv0)));
            asm("mov.b64 %0, {%1, %1};" : "=l"(xx1) : "r"(__float_as_uint(xv1)));
            int kk = (h * 4 + it) * 16 + k;
            int wb = kk * 8 + h;
#pragma unroll
            for (int q8 = 0; q8 < 8; q8++) {
                ull wv = wsu[wb + q8];
                asm("fma.rn.f32x2 %0, %1, %2, %0;" : "+l"(a0[q8]) : "l"(xx0), "l"(wv));
                asm("fma.rn.f32x2 %0, %1, %2, %0;" : "+l"(a1[q8]) : "l"(xx1), "l"(wv));
            }
        }
    }
#pragma unroll
    for (int q8 = 0; q8 < 8; q8++) {
        ull o0 = __shfl_xor_sync(0xFFFFFFFFu, a0[q8], 1);
        ull o1 = __shfl_xor_sync(0xFFFFFFFFu, a1[q8], 1);
        asm("add.rn.f32x2 %0, %0, %1;" : "+l"(a0[q8]) : "l"(o0));
        asm("add.rn.f32x2 %0, %0, %1;" : "+l"(a1[q8]) : "l"(o1));
    }
    if (h == 0) {
        int n0 = base + p * 2;
        if (n0 < NN) {
            ull* o = (ull*)(d_h0 + (size_t)n0 * HID);
#pragma unroll
            for (int q8 = 0; q8 < 8; q8++) o[q8] = a0[q8];
        }
        if (n0 + 1 < NN) {
            ull* o = (ull*)(d_h0 + (size_t)(n0 + 1) * HID);
#pragma unroll
            for (int q8 = 0; q8 < 8; q8++) o[q8] = a1[q8];
        }
    }
}

// count in-degrees; record each edge's rank within its dst bucket (coalesced)
__global__ void kcount(const int* __restrict__ ei) {
    int e4 = blockIdx.x * blockDim.x + threadIdx.x;
    int4 d = ((const int4*)(ei + EE))[e4];
    int4 r;
    r.x = atomicAdd(&d_cnt[d.x], 1);
    r.y = atomicAdd(&d_cnt[d.y], 1);
    r.z = atomicAdd(&d_cnt[d.z], 1);
    r.w = atomicAdd(&d_cnt[d.w], 1);
    ((int4*)d_rank)[e4] = r;
}

// block sums of cnt
__global__ void __launch_bounds__(SBLK) kscanA() {
    __shared__ int ws[32];
    int i = blockIdx.x * SBLK + threadIdx.x;
    int lane = threadIdx.x & 31, wd = threadIdx.x >> 5;
    int v = (i < NN) ? d_cnt[i] : 0;
    int s = v;
#pragma unroll
    for (int o = 16; o; o >>= 1) s += __shfl_xor_sync(0xFFFFFFFFu, s, o);
    if (lane == 0) ws[wd] = s;
    __syncthreads();
    if (wd == 0) {
        int s2 = ws[lane];
#pragma unroll
        for (int o = 16; o; o >>= 1) s2 += __shfl_xor_sync(0xFFFFFFFFu, s2, o);
        if (lane == 0) d_bsum[blockIdx.x] = s2;
    }
}

// fused: per-block offset from bsum + local exclusive scan + derived arrays;
// re-zeroes cnt for the next execution.
__global__ void __launch_bounds__(SBLK) kscanC() {
    __shared__ int ws[32];
    __shared__ int off_s;
    int bid = blockIdx.x;
    int t = threadIdx.x, lane = t & 31, wd = t >> 5;
    if (wd == 0) {
        int acc = 0;
        for (int b = lane; b < bid; b += 32) acc += d_bsum[b];
#pragma unroll
        for (int o = 16; o; o >>= 1) acc += __shfl_xor_sync(0xFFFFFFFFu, acc, o);
        if (lane == 0) {
            off_s = acc;
            if (bid == NBLK - 1) d_rowptr[NN] = acc + d_bsum[NBLK - 1];
        }
    }
    int i = bid * SBLK + t;
    int v = (i < NN) ? d_cnt[i] : 0;
    int xv = v;
#pragma unroll
    for (int o = 1; o < 32; o <<= 1) {
        int y = __shfl_up_sync(0xFFFFFFFFu, xv, o);
        if (lane >= o) xv += y;
    }
    if (lane == 31) ws[wd] = xv;
    __syncthreads();
    if (wd == 0) {
        int s2 = ws[lane];
#pragma unroll
        for (int o = 1; o < 32; o <<= 1) {
            int y = __shfl_up_sync(0xFFFFFFFFu, s2, o);
            if (lane >= o) s2 += y;
        }
        ws[lane] = s2;
    }
    __syncthreads();
    int excl = xv - v + (wd > 0 ? ws[wd - 1] : 0) + off_s;
    if (i < NN) {
        d_rowptr[i] = excl;
        d_dinv[i] = rsqrt_acc((float)(v + 1));
        d_nidx[i] = -1;
        d_cnt[i] = 0;      // restore invariant for next execution
    }
}

// atomic-free scatter: position = rowptr[dst] + rank[edge]
__global__ void kscatter(const int* __restrict__ ei) {
    int e4 = blockIdx.x * blockDim.x + threadIdx.x;
    int4 s = ((const int4*)ei)[e4];
    int4 d = ((const int4*)(ei + EE))[e4];
    int4 r = ((const int4*)d_rank)[e4];
    d_csr[d_rowptr[d.x] + r.x] = s.x;
    d_csr[d_rowptr[d.y] + r.y] = s.y;
    d_csr[d_rowptr[d.z] + r.z] = s.z;
    d_csr[d_rowptr[d.w] + r.w] = s.w;
}

// conv1 (+relu) fp32 Kahan accumulation, 4-way unrolled; score linear terms
__global__ void kconv1(const float* __restrict__ b1, const float* __restrict__ pw1,
                       const float* __restrict__ pw2, const float* __restrict__ pb) {
    int gw = (blockIdx.x * blockDim.x + threadIdx.x) >> 5;
    if (gw >= NN) return;
    int lane = threadIdx.x & 31, half = lane >> 4, ch = lane & 15;
    int st = d_rowptr[gw], en = d_rowptr[gw + 1];
    float s0a = 0.f, c0a = 0.f, s1a = 0.f, c1a = 0.f;
    float s2a = 0.f, c2a = 0.f, s3a = 0.f, c3a = 0.f;
    int e = st + half;
    for (; e + 6 < en; e += 8) {
        int n0 = d_csr[e], n1 = d_csr[e + 2], n2 = d_csr[e + 4], n3 = d_csr[e + 6];
        kadd(s0a, c0a, d_dinv[n0] * d_h0[n0 * HID + ch]);
        kadd(s1a, c1a, d_dinv[n1] * d_h0[n1 * HID + ch]);
        kadd(s2a, c2a, d_dinv[n2] * d_h0[n2 * HID + ch]);
        kadd(s3a, c3a, d_dinv[n3] * d_h0[n3 * HID + ch]);
    }
    for (; e < en; e += 2) {
        int n0 = d_csr[e];
        kadd(s0a, c0a, d_dinv[n0] * d_h0[n0 * HID + ch]);
    }
    kadd(s0a, c0a, s1a); kadd(s0a, c0a, -c1a);
    kadd(s0a, c0a, s2a); kadd(s0a, c0a, -c2a);
    kadd(s0a, c0a, s3a); kadd(s0a, c0a, -c3a);
    float os = __shfl_xor_sync(0xFFFFFFFFu, s0a, 16);
    float oc = __shfl_xor_sync(0xFFFFFFFFu, c0a, 16);
    kadd(s0a, c0a, os); kadd(s0a, c0a, -oc);
    float a = s0a - c0a;
    float degf = (float)(en - st + 1);
    float hv = d_dinv[gw] * a + d_h0[gw * HID + ch] / degf + b1[ch];
    hv = fmaxf(hv, 0.f);
    if (half == 0) d_h[gw * HID + ch] = hv;
    float u1 = hv * pw1[ch];
    float u2 = hv * pw2[ch];
#pragma unroll
    for (int o = 8; o; o >>= 1) {
        u1 += __shfl_xor_sync(0xFFFFFFFFu, u1, o);
        u2 += __shfl_xor_sync(0xFFFFFFFFu, u2, o);
    }
    if (lane == 0) { d_spart[gw] = u1 + pb[0]; d_t2[gw] = u2; }
}

// score = spart + sum_{in-neighbors} t2 (Kahan); build sort key
__global__ void kpool() {
    int gw = (blockIdx.x * blockDim.x + threadIdx.x) >> 5;
    if (gw >= NN) return;
    int lane = threadIdx.x & 31;
    int st = d_rowptr[gw], en = d_rowptr[gw + 1];
    float sum = 0.f, comp = 0.f;
    for (int e = st + lane; e < en; e += 32) kadd(sum, comp, d_t2[d_csr[e]]);
#pragma unroll
    for (int o = 16; o; o >>= 1) {
        float os = __shfl_xor_sync(0xFFFFFFFFu, sum, o);
        float oc = __shfl_xor_sync(0xFFFFFFFFu, comp, o);
        kadd(sum, comp, os); kadd(sum, comp, -oc);
    }
    if (lane == 0) {
        float sv = d_spart[gw] + (sum - comp);
        d_s[gw] = sv;
        unsigned u = __float_as_uint(sv);
        u = (u & 0x80000000u) ? ~u : (u | 0x80000000u);
        d_keys[gw] = ((ull)u << 32) | (ull)(~(unsigned)gw);
    }
}

// bitonic sort, descending, SSIZE keys (tail = all-zero padding keys)
__global__ void __launch_bounds__(1024) ksort_init() {
    __shared__ ull sk[TILE];
    int base = blockIdx.x * TILE;
    for (int i = threadIdx.x; i < TILE; i += 1024) sk[i] = d_keys[base + i];
    __syncthreads();
    for (int k = 2; k <= TILE; k <<= 1)
        for (int j = k >> 1; j > 0; j >>= 1) {
            for (int i = threadIdx.x; i < TILE; i += 1024) {
                int p = i ^ j;
                if (p > i) {
                    bool desc = (((base + i) & k) == 0);
                    ull A = sk[i], B = sk[p];
                    if ((A < B) == desc) { sk[i] = B; sk[p] = A; }
                }
            }
            __syncthreads();
        }
    for (int i = threadIdx.x; i < TILE; i += 1024) d_keys[base + i] = sk[i];
}

// all global steps (j >= 4096) of phase k, fused.
__global__ void __launch_bounds__(1024) kcol(int k) {
    __shared__ ull sk[4096];          // [m][low] : 32 x 128
    int lowbase = blockIdx.x * 128;
    for (int idx = threadIdx.x; idx < 4096; idx += 1024) {
        int m = idx >> 7, low = idx & 127;
        sk[idx] = d_keys[m * 4096 + lowbase + low];
    }
    __syncthreads();
    int kp = k >> 12;                 // k' in units of 4096
    for (int jp = kp >> 1; jp >= 1; jp >>= 1) {
        for (int q = threadIdx.x; q < 2048; q += 1024) {
            int low = q & 127;
            int mg = q >> 7;          // 0..15
            int m = ((mg & ~(jp - 1)) << 1) | (mg & (jp - 1));
            int p = m | jp;
            bool desc = ((m & kp) == 0);
            ull A = sk[m * 128 + low], B = sk[p * 128 + low];
            if ((A < B) == desc) { sk[m * 128 + low] = B; sk[p * 128 + low] = A; }
        }
        __syncthreads();
    }
    for (int idx = threadIdx.x; idx < 4096; idx += 1024) {
        int m = idx >> 7, low = idx & 127;
        d_keys[m * 4096 + lowbase + low] = sk[idx];
    }
}

__global__ void __launch_bounds__(1024) ksort_merge(int k) {
    __shared__ ull sk[TILE];
    int base = blockIdx.x * TILE;
    for (int i = threadIdx.x; i < TILE; i += 1024) sk[i] = d_keys[base + i];
    __syncthreads();
    for (int j = TILE >> 1; j > 0; j >>= 1) {
        for (int i = threadIdx.x; i < TILE; i += 1024) {
            int p = i ^ j;
            if (p > i) {
                bool desc = (((base + i) & k) == 0);
                ull A = sk[i], B = sk[p];
                if ((A < B) == desc) { sk[i] = B; sk[p] = A; }
            }
        }
        __syncthreads();
    }
    for (int i = threadIdx.x; i < TILE; i += 1024) d_keys[base + i] = sk[i];
}

// top-K select: perm, inverse map, h2v[orig id] = tanh(s) * (h @ w2)
__global__ void kselect(const float* __restrict__ w2) {
    int r = (blockIdx.x * blockDim.x + threadIdx.x) >> 5;
    if (r >= KK) return;
    int lane = threadIdx.x & 31;
    ull key = d_keys[r];
    int idx = (int)(~(unsigned)(key & 0xFFFFFFFFull));
    if (lane == 0) { d_nidx[idx] = r; d_perm[r] = idx; }
    if (lane < NCLS) {
        float th = tanhf(d_s[idx]);
        float acc = 0.f;
#pragma unroll
        for (int j = 0; j < HID; j++)
            acc += d_h[idx * HID + j] * w2[j * NCLS + lane];
        ((float*)d_h2v)[idx * 12 + lane] = th * acc;
    }
}

// surviving-degree of kept nodes; pre-scale h2v rows by dinv2
__global__ void kdeg2() {
    int r = (blockIdx.x * blockDim.x + threadIdx.x) >> 5;
    if (r >= KK) return;
    int lane = threadIdx.x & 31;
    int i = d_perm[r];
    int st = d_rowptr[i], en = d_rowptr[i + 1];
    int cnt = 0;
    for (int e = st + lane; e < en; e += 32) cnt += (d_nidx[d_csr[e]] >= 0);
#pragma unroll
    for (int o = 16; o; o >>= 1) cnt += __shfl_xor_sync(0xFFFFFFFFu, cnt, o);
    float d2 = rsqrt_acc((float)(cnt + 1));
    if (lane == 0) d_dinv2[r] = d2;
    if (lane < 12) ((float*)d_h2v)[i * 12 + lane] *= d2;
}

// conv2: branch-free float4 gathers from dense h2v + relu + log_softmax
__global__ void kconv2(const float* __restrict__ b2, float* __restrict__ out) {
    __shared__ __align__(16) float red[8][12];
    int r = (blockIdx.x * blockDim.x + threadIdx.x) >> 5;
    if (r >= KK) return;
    int lane = threadIdx.x & 31, wip = (threadIdx.x >> 5) & 7;
    int i = d_perm[r];
    int st = d_rowptr[i], en = d_rowptr[i + 1];
    const float* h2vf = (const float*)d_h2v;
    float4 a0 = {0,0,0,0}, a1 = {0,0,0,0}, a2 = {0,0,0,0};
    for (int e = st + lane; e < en; e += 32) {
        int n = d_csr[e];
        const float4* row = (const float4*)(h2vf + n * 12);
        float4 v0 = row[0], v1 = row[1], v2 = row[2];
        a0.x += v0.x; a0.y += v0.y; a0.z += v0.z; a0.w += v0.w;
        a1.x += v1.x; a1.y += v1.y; a1.z += v1.z; a1.w += v1.w;
        a2.x += v2.x; a2.y += v2.y; a2.z += v2.z; a2.w += v2.w;
    }
#pragma unroll
    for (int o = 16; o; o >>= 1) {
        a0.x += __shfl_xor_sync(0xFFFFFFFFu, a0.x, o);
        a0.y += __shfl_xor_sync(0xFFFFFFFFu, a0.y, o);
        a0.z += __shfl_xor_sync(0xFFFFFFFFu, a0.z, o);
        a0.w += __shfl_xor_sync(0xFFFFFFFFu, a0.w, o);
        a1.x += __shfl_xor_sync(0xFFFFFFFFu, a1.x, o);
        a1.y += __shfl_xor_sync(0xFFFFFFFFu, a1.y, o);
        a1.z += __shfl_xor_sync(0xFFFFFFFFu, a1.z, o);
        a1.w += __shfl_xor_sync(0xFFFFFFFFu, a1.w, o);
        a2.x += __shfl_xor_sync(0xFFFFFFFFu, a2.x, o);
        a2.y += __shfl_xor_sync(0xFFFFFFFFu, a2.y, o);
    }
    if (lane == 0) {
        ((float4*)red[wip])[0] = a0;
        ((float4*)red[wip])[1] = a1;
        ((float4*)red[wip])[2] = a2;
    }
    __syncwarp();
    bool act = lane < NCLS;
    float own = act ? h2vf[i * 12 + lane] : 0.f;
    float v = act
        ? fmaxf(d_dinv2[r] * (red[wip][lane] + own) + b2[lane], 0.f)
        : -1e30f;
    float m = v;
#pragma unroll
    for (int o = 8; o; o >>= 1)
        m = fmaxf(m, __shfl_xor_sync(0xFFFFFFFFu, m, o, 16));
    float ex = act ? expf(v - m) : 0.f;
#pragma unroll
    for (int o = 8; o; o >>= 1)
        ex += __shfl_xor_sync(0xFFFFFFFFu, ex, o, 16);
    if (act) out[r * NCLS + lane] = v - m - logf(ex);
}

extern "C" void kernel_launch(void* const* d_in, const int* in_sizes, int n_in,
                              void* d_out, int out_size) {
    const float* x  = (const float*)d_in[0];
    const int*   ei = (const int*)d_in[1];
    const float* w1 = (const float*)d_in[2];
    const float* b1 = (const float*)d_in[3];
    const float* pw1 = (const float*)d_in[4];
    const float* pw2 = (const float*)d_in[5];
    const float* pb = (const float*)d_in[6];
    const float* w2 = (const float*)d_in[7];
    const float* b2 = (const float*)d_in[8];
    float* out = (float*)d_out;

    kcount<<<EE / 1024, 256>>>(ei);
    kscanA<<<NBLK, SBLK>>>();
    kscanC<<<NBLK, SBLK>>>();
    kscatter<<<EE / 1024, 256>>>(ei);           // slot 4: gets profiled
    kgemm1<<<(NN + 255) / 256, 256>>>(x, w1);
    kconv1<<<NN * 32 / 256, 256>>>(b1, pw1, pw2, pb);
    kpool<<<NN * 32 / 256, 256>>>();

    ksort_init<<<SSIZE / TILE, 1024>>>();
    for (int k = TILE * 2; k <= SSIZE; k <<= 1) {
        kcol<<<SSIZE / 4096, 1024>>>(k);
        ksort_merge<<<SSIZE / TILE, 1024>>>(k);
    }

    kselect<<<KK * 32 / 256, 256>>>(w2);
    kdeg2<<<KK * 32 / 256, 256>>>();
    kconv2<<<KK * 32 / 256, 256>>>(b2, out);
}